// round 1
// baseline (speedup 1.0000x reference)
#include <cuda_runtime.h>
#include <float.h>
#include <math.h>

#define NB 8
#define NP 2048
#define ND 512
#define NK 16

// Scratch (device globals -- no allocation allowed in kernel_launch)
__device__ float g_fq[NB * NP * ND];                 // normalized ffq
__device__ float g_fp[NB * NP * ND];                 // normalized ffp
__device__ float g_w1[(size_t)NB * NP * NP];         // similarity matrix
__device__ int   g_idx[NB * NP * NK];                // top-k indices

// ---------------------------------------------------------------------------
// Normalize rows of [B*N, D] by (L2 norm + 1e-8). One warp per row.
// which: 0 -> write g_fp, 1 -> write g_fq
// ---------------------------------------------------------------------------
__global__ void k_normalize(const float* __restrict__ src, int which) {
    int row  = blockIdx.x * 8 + (threadIdx.x >> 5);
    int lane = threadIdx.x & 31;
    const float* s = src + (size_t)row * ND;
    float ss = 0.f;
    for (int d = lane; d < ND; d += 32) { float v = s[d]; ss = fmaf(v, v, ss); }
#pragma unroll
    for (int o = 16; o; o >>= 1) ss += __shfl_xor_sync(0xffffffffu, ss, o);
    float inv = 1.0f / (sqrtf(ss) + 1e-8f);
    float* dst = (which ? g_fq : g_fp) + (size_t)row * ND;
    for (int d = lane; d < ND; d += 32) dst[d] = s[d] * inv;
}

// ---------------------------------------------------------------------------
// C[b] = A[b] * B[b]^T  (both row-major [N, D]) -> [N, N]
// 128x128 tile, k-chunk 16, 256 threads, 8x8 per thread.
// Accumulation is strictly sequential over d (matches simple fp32 summation).
// ---------------------------------------------------------------------------
__global__ __launch_bounds__(256, 2) void k_gemm() {
    const int bz = blockIdx.z;
    const float* A  = g_fq + (size_t)bz * NP * ND;
    const float* Bm = g_fp + (size_t)bz * NP * ND;
    float* C = g_w1 + (size_t)bz * NP * NP;

    __shared__ float As[16][128];
    __shared__ float Bs[16][128];

    const int tid = threadIdx.x;
    const int q0 = blockIdx.y * 128;
    const int p0 = blockIdx.x * 128;
    const int ty = tid >> 4;      // 0..15
    const int tx = tid & 15;      // 0..15

    float acc[8][8];
#pragma unroll
    for (int i = 0; i < 8; i++)
#pragma unroll
        for (int j = 0; j < 8; j++) acc[i][j] = 0.f;

    const int lrow0 = tid >> 2;           // 0..63
    const int lk    = (tid & 3) * 4;      // 0,4,8,12

    for (int kc = 0; kc < ND; kc += 16) {
#pragma unroll
        for (int l = 0; l < 2; l++) {
            int row = lrow0 + l * 64;
            float4 va = *(const float4*)(A  + (size_t)(q0 + row) * ND + kc + lk);
            As[lk + 0][row] = va.x; As[lk + 1][row] = va.y;
            As[lk + 2][row] = va.z; As[lk + 3][row] = va.w;
            float4 vb = *(const float4*)(Bm + (size_t)(p0 + row) * ND + kc + lk);
            Bs[lk + 0][row] = vb.x; Bs[lk + 1][row] = vb.y;
            Bs[lk + 2][row] = vb.z; Bs[lk + 3][row] = vb.w;
        }
        __syncthreads();
#pragma unroll
        for (int kk = 0; kk < 16; kk++) {
            float a[8], bv[8];
            *(float4*)&a[0]  = *(const float4*)&As[kk][ty * 8];
            *(float4*)&a[4]  = *(const float4*)&As[kk][ty * 8 + 4];
            *(float4*)&bv[0] = *(const float4*)&Bs[kk][tx * 8];
            *(float4*)&bv[4] = *(const float4*)&Bs[kk][tx * 8 + 4];
#pragma unroll
            for (int i = 0; i < 8; i++)
#pragma unroll
                for (int j = 0; j < 8; j++)
                    acc[i][j] = fmaf(a[i], bv[j], acc[i][j]);
        }
        __syncthreads();
    }

#pragma unroll
    for (int i = 0; i < 8; i++) {
        float* cr = C + (size_t)(q0 + ty * 8 + i) * NP + p0 + tx * 8;
        *(float4*)cr       = make_float4(acc[i][0], acc[i][1], acc[i][2], acc[i][3]);
        *(float4*)(cr + 4) = make_float4(acc[i][4], acc[i][5], acc[i][6], acc[i][7]);
    }
}

// ---------------------------------------------------------------------------
// Top-16 per row of w1, descending, ties -> lower index (lax.top_k order).
// One 256-thread block per row; 16 iterations of block argmax over smem copy.
// Writes int indices to g_idx and float-cast indices into the output buffer.
// ---------------------------------------------------------------------------
__global__ void k_topk(float* __restrict__ fidx_out) {
    const int row = blockIdx.x;
    const float* r = g_w1 + (size_t)row * NP;
    __shared__ float sv[NP];
    __shared__ float rv[256];
    __shared__ int   ri[256];
    const int tid = threadIdx.x;

    for (int d = tid; d < NP; d += 256) sv[d] = r[d];
    __syncthreads();

    for (int it = 0; it < NK; it++) {
        float best = -FLT_MAX;
        int bi = NP;
        for (int d = tid; d < NP; d += 256) {   // ascending: keeps lowest idx on ties
            float v = sv[d];
            if (v > best) { best = v; bi = d; }
        }
        rv[tid] = best; ri[tid] = bi;
        __syncthreads();
        for (int s = 128; s > 0; s >>= 1) {
            if (tid < s) {
                float v2 = rv[tid + s]; int i2 = ri[tid + s];
                if (v2 > rv[tid] || (v2 == rv[tid] && i2 < ri[tid])) {
                    rv[tid] = v2; ri[tid] = i2;
                }
            }
            __syncthreads();
        }
        if (tid == 0) {
            int m = ri[0];
            g_idx[row * NK + it]    = m;
            fidx_out[row * NK + it] = (float)m;
            sv[m] = -FLT_MAX;
        }
        __syncthreads();
    }
}

// ---------------------------------------------------------------------------
// 3x3 inverse (adjugate) applied to a vector: o = inv(M) * v
// ---------------------------------------------------------------------------
__device__ __forceinline__ void inv3_apply(const float* __restrict__ M,
                                           const float* __restrict__ v,
                                           float* __restrict__ o) {
    float a = M[0], b = M[1], c = M[2];
    float d = M[3], e = M[4], f = M[5];
    float g = M[6], h = M[7], i = M[8];
    float A  = e * i - f * h;
    float Bc = -(d * i - f * g);
    float Cc = d * h - e * g;
    float det = a * A + b * Bc + c * Cc;
    float id = 1.0f / det;
    float i00 = A * id,  i01 = -(b * i - c * h) * id, i02 = (b * f - c * e) * id;
    float i10 = Bc * id, i11 = (a * i - c * g) * id,  i12 = -(a * f - c * d) * id;
    float i20 = Cc * id, i21 = -(a * h - b * g) * id, i22 = (a * e - b * d) * id;
    o[0] = i00 * v[0] + i01 * v[1] + i02 * v[2];
    o[1] = i10 * v[0] + i11 * v[1] + i12 * v[2];
    o[2] = i20 * v[0] + i21 * v[1] + i22 * v[2];
}

// ---------------------------------------------------------------------------
// Per point: gather top-K rows of ffp, avg/max pool over K, pointwise linear
// with W[3,1536] on [ffq | avg | max], rotate back by inv(R1) then inv(R2),
// mask by (centroids >= N), add q. Writes q_refine twice (outputs 2 and 3).
// One 256-thread block per point; each thread owns 2 feature channels.
// ---------------------------------------------------------------------------
__global__ __launch_bounds__(256) void k_agg(
    const float* __restrict__ ffp, const float* __restrict__ ffq,
    const float* __restrict__ R1,  const float* __restrict__ R2,
    const int*   __restrict__ cen, const float* __restrict__ W,
    const float* __restrict__ bvec, const float* __restrict__ q,
    float* __restrict__ out)
{
    const int pt  = blockIdx.x;       // b*N + n
    const int b   = pt >> 11;         // /2048
    const int tid = threadIdx.x;

    __shared__ int sidx[NK];
    if (tid < NK) sidx[tid] = g_idx[pt * NK + tid];
    __syncthreads();

    const float* fpb = ffp + (size_t)b * NP * ND;
    const float* fqr = ffq + (size_t)pt * ND;

    float pv0 = 0.f, pv1 = 0.f, pv2 = 0.f;
#pragma unroll
    for (int rr = 0; rr < 2; rr++) {
        int d = tid + rr * 256;
        float s = 0.f, mx = -FLT_MAX;
#pragma unroll
        for (int k = 0; k < NK; k++) {
            float v = fpb[(size_t)sidx[k] * ND + d];
            s += v;
            mx = fmaxf(mx, v);
        }
        float avg = s * (1.0f / 16.0f);
        float fv  = fqr[d];
        pv0 += W[d] * fv        + W[512 + d] * avg        + W[1024 + d] * mx;
        pv1 += W[1536 + d] * fv + W[1536 + 512 + d] * avg + W[1536 + 1024 + d] * mx;
        pv2 += W[3072 + d] * fv + W[3072 + 512 + d] * avg + W[3072 + 1024 + d] * mx;
    }
#pragma unroll
    for (int o = 16; o; o >>= 1) {
        pv0 += __shfl_xor_sync(0xffffffffu, pv0, o);
        pv1 += __shfl_xor_sync(0xffffffffu, pv1, o);
        pv2 += __shfl_xor_sync(0xffffffffu, pv2, o);
    }
    __shared__ float w0[8], w1s[8], w2[8];
    int wid = tid >> 5, lane = tid & 31;
    if (lane == 0) { w0[wid] = pv0; w1s[wid] = pv1; w2[wid] = pv2; }
    __syncthreads();

    if (tid == 0) {
        float v0 = bvec[0], v1 = bvec[1], v2 = bvec[2];
#pragma unroll
        for (int i = 0; i < 8; i++) { v0 += w0[i]; v1 += w1s[i]; v2 += w2[i]; }
        float vin[3] = {v0, v1, v2}, t1[3], t2[3];
        inv3_apply(R1 + (size_t)pt * 9, vin, t1);
        inv3_apply(R2 + (size_t)pt * 9, t1, t2);
        float m = (cen[pt] >= NP) ? 1.0f : 0.0f;
#pragma unroll
        for (int j = 0; j < 3; j++) {
            float qr = q[pt * 3 + j] + t2[j] * m;
            out[49152 + pt * 3 + j] = qr;   // output 2: q_refine
            out[98304 + pt * 3 + j] = qr;   // output 3: q_refine
        }
    }
}

// ---------------------------------------------------------------------------
// Launch.  Inputs (metadata order): p, q, ffp, ffq, R1, R2, centroids, W, b
// Output: concat(q[49152], q_refine[49152], q_refine[49152], idx[262144]) f32
// ---------------------------------------------------------------------------
extern "C" void kernel_launch(void* const* d_in, const int* in_sizes, int n_in,
                              void* d_out, int out_size) {
    const float* q   = (const float*)d_in[1];
    const float* ffp = (const float*)d_in[2];
    const float* ffq = (const float*)d_in[3];
    const float* R1  = (const float*)d_in[4];
    const float* R2  = (const float*)d_in[5];
    const int*   cen = (const int*)d_in[6];
    const float* W   = (const float*)d_in[7];
    const float* bb  = (const float*)d_in[8];
    float* out = (float*)d_out;

    // normalize ffp -> g_fp, ffq -> g_fq  (one warp per row; 8 rows/block)
    k_normalize<<<NB * NP / 8, 256>>>(ffp, 0);
    k_normalize<<<NB * NP / 8, 256>>>(ffq, 1);

    // similarity GEMM: w1[b] = fq[b] @ fp[b]^T
    dim3 gg(NP / 128, NP / 128, NB);
    k_gemm<<<gg, 256>>>();

    // top-16 per row; writes idx (as float) into out[147456..]
    k_topk<<<NB * NP, 256>>>(out + 3 * NB * NP * 3);

    // pooling + refine + rotate-back; writes q_refine twice
    k_agg<<<NB * NP, 256>>>(ffp, ffq, R1, R2, cen, W, bb, q, out);

    // output 1: q passthrough
    cudaMemcpyAsync(out, q, (size_t)NB * NP * 3 * sizeof(float),
                    cudaMemcpyDeviceToDevice);
}

// round 5
// speedup vs baseline: 1.9314x; 1.9314x over previous
#include <cuda_runtime.h>
#include <cuda_fp16.h>
#include <float.h>
#include <math.h>
#include <stdint.h>

#define NB 8
#define NP 2048
#define ND 512
#define NK 16
#define NCAND 32

// ---------------- device scratch (no allocations allowed) -------------------
__device__ __half g_fqh[(size_t)NB * NP * ND];        // normalized ffq, fp16
__device__ __half g_fph[(size_t)NB * NP * ND];        // normalized ffp, fp16
__device__ float  g_nq[NB * NP];                      // 1/(||ffq||+eps)
__device__ float  g_np[NB * NP];                      // 1/(||ffp||+eps)
__device__ __half g_w1h[(size_t)NB * NP * NP];        // similarity, fp16
__device__ int    g_cand[NB * NP * NCAND];            // top-32 candidates per row

// ---------------- helpers ---------------------------------------------------
__device__ __forceinline__ uint32_t smem_u32(const void* p) {
    uint32_t a;
    asm("{ .reg .u64 t; cvta.to.shared.u64 t, %1; cvt.u32.u64 %0, t; }" : "=r"(a) : "l"(p));
    return a;
}
#define SWZ(off) ((off) ^ (((off) >> 3) & 0x70))

__device__ __forceinline__ void cp16(uint32_t dst, const void* src) {
    asm volatile("cp.async.cg.shared.global [%0], [%1], 16;" :: "r"(dst), "l"(src));
}
#define CP_COMMIT() asm volatile("cp.async.commit_group;" ::: "memory")
#define CP_WAIT(n)  asm volatile("cp.async.wait_group %0;" :: "n"(n) : "memory")

#define LDSM4(r, addr)                                                          \
    asm volatile("ldmatrix.sync.aligned.m8n8.x4.shared.b16 {%0,%1,%2,%3}, [%4];" \
        : "=r"((r)[0]), "=r"((r)[1]), "=r"((r)[2]), "=r"((r)[3]) : "r"(addr))

__device__ __forceinline__ void mma16816(float* d, const uint32_t* a,
                                         uint32_t b0, uint32_t b1) {
    asm volatile(
        "mma.sync.aligned.m16n8k16.row.col.f32.f16.f16.f32 "
        "{%0,%1,%2,%3},{%4,%5,%6,%7},{%8,%9},{%0,%1,%2,%3};"
        : "+f"(d[0]), "+f"(d[1]), "+f"(d[2]), "+f"(d[3])
        : "r"(a[0]), "r"(a[1]), "r"(a[2]), "r"(a[3]), "r"(b0), "r"(b1));
}

// ---------------------------------------------------------------------------
// Normalize rows by (L2 + 1e-8). Norm reduction uses the EXACT arithmetic of
// the validated R1 kernel (lane-strided scalar fmaf + xor butterfly).
// Writes fp16 normalized copy + fp32 inv norm.
// ---------------------------------------------------------------------------
__global__ void k_normalize(const float* __restrict__ src, __half* __restrict__ dst,
                            float* __restrict__ invn) {
    int row  = blockIdx.x * 8 + (threadIdx.x >> 5);
    int lane = threadIdx.x & 31;
    const float* s = src + (size_t)row * ND;
    float ss = 0.f;
    for (int d = lane; d < ND; d += 32) { float v = s[d]; ss = fmaf(v, v, ss); }
#pragma unroll
    for (int o = 16; o; o >>= 1) ss += __shfl_xor_sync(0xffffffffu, ss, o);
    float inv = 1.0f / (sqrtf(ss) + 1e-8f);
    if (lane == 0) invn[row] = inv;
    const float2* s2 = (const float2*)s;
    __half2* d2 = (__half2*)(dst + (size_t)row * ND);
#pragma unroll
    for (int i = 0; i < 8; i++) {
        float2 v = s2[lane + 32 * i];
        d2[lane + 32 * i] = __floats2half2_rn(v.x * inv, v.y * inv);
    }
}

// ---------------------------------------------------------------------------
// HMMA fp16 GEMM: w1[b] = fq[b] @ fp[b]^T -> fp16.
// 128x128 tile, BK=64, cp.async double buffer, 8 warps in 4(M) x 2(N),
// warp tile 32x64, mma.m16n8k16, fp32 accumulate.
// ---------------------------------------------------------------------------
#define BM 128
#define BN 128
#define BK 64

__global__ __launch_bounds__(256) void k_gemm_hmma() {
    extern __shared__ char sm[];
    const uint32_t sb = smem_u32(sm);
    const int tid = threadIdx.x, lane = tid & 31, wid = tid >> 5;
    const int wm = wid & 3, wn = wid >> 2;
    const int bz = blockIdx.z;
    const __half* Ag = g_fqh + ((size_t)bz * NP + blockIdx.y * BM) * ND;
    const __half* Bg = g_fph + ((size_t)bz * NP + blockIdx.x * BN) * ND;

    auto load = [&](int kc, int buf) {
        uint32_t abase = sb + buf * 32768;
        const __half* ap = Ag + kc * BK;
#pragma unroll
        for (int i = 0; i < 4; i++) {
            int id = tid + i * 256;
            int r = id >> 3, c = id & 7;
            cp16(abase + SWZ(r * 128 + c * 16), ap + (size_t)r * ND + c * 8);
        }
        uint32_t bbase = abase + 16384;
        const __half* bp = Bg + kc * BK;
#pragma unroll
        for (int i = 0; i < 4; i++) {
            int id = tid + i * 256;
            int r = id >> 3, c = id & 7;
            cp16(bbase + SWZ(r * 128 + c * 16), bp + (size_t)r * ND + c * 8);
        }
    };

    float acc[2][8][4];
#pragma unroll
    for (int t = 0; t < 2; t++)
#pragma unroll
        for (int n = 0; n < 8; n++)
#pragma unroll
            for (int i = 0; i < 4; i++) acc[t][n][i] = 0.f;

    load(0, 0);
    CP_COMMIT();

    const int lrow = lane & 15;
    const int lk16 = (lane >> 4) * 16;

#pragma unroll 1
    for (int c = 0; c < 8; c++) {
        int buf = c & 1;
        if (c < 7) { load(c + 1, buf ^ 1); CP_COMMIT(); CP_WAIT(1); }
        else       { CP_WAIT(0); }
        __syncthreads();
        uint32_t Asb = sb + buf * 32768;
        uint32_t Bsb = Asb + 16384;
#pragma unroll
        for (int ks = 0; ks < 4; ks++) {
            uint32_t a[2][4];
#pragma unroll
            for (int t = 0; t < 2; t++) {
                int row = wm * 32 + t * 16 + lrow;
                uint32_t off = (uint32_t)(row * 128 + ks * 32 + lk16) ^ ((row & 7) << 4);
                LDSM4(a[t], Asb + off);
            }
            uint32_t bfr[4][4];
#pragma unroll
            for (int j = 0; j < 4; j++) {
                int row = wn * 64 + j * 16 + lrow;
                uint32_t off = (uint32_t)(row * 128 + ks * 32 + lk16) ^ ((row & 7) << 4);
                LDSM4(bfr[j], Bsb + off);
            }
#pragma unroll
            for (int t = 0; t < 2; t++)
#pragma unroll
                for (int n8 = 0; n8 < 8; n8++) {
                    int j = n8 >> 1, hi = n8 & 1;
                    mma16816(acc[t][n8], a[t], bfr[j][hi ? 1 : 0], bfr[j][hi ? 3 : 2]);
                }
        }
        __syncthreads();
    }

    const int q0 = blockIdx.y * BM, p0 = blockIdx.x * BN;
#pragma unroll
    for (int t = 0; t < 2; t++)
#pragma unroll
        for (int n8 = 0; n8 < 8; n8++) {
            int m = q0 + wm * 32 + t * 16 + (lane >> 2);
            int n = p0 + wn * 64 + n8 * 8 + (lane & 3) * 2;
            size_t base = ((size_t)bz * NP + m) * NP + n;
            *(__half2*)(g_w1h + base) =
                __floats2half2_rn(acc[t][n8][0], acc[t][n8][1]);
            *(__half2*)(g_w1h + base + (size_t)8 * NP) =
                __floats2half2_rn(acc[t][n8][2], acc[t][n8][3]);
        }
}

// ---------------------------------------------------------------------------
// Per-row top-32 candidates from fp16 w1 (set only; order fixed by rescore).
// One warp per row; row register-resident. Iterative argmax.
// ---------------------------------------------------------------------------
__global__ __launch_bounds__(256) void k_cand() {
    int row  = blockIdx.x * 8 + (threadIdx.x >> 5);
    int lane = threadIdx.x & 31;
    const unsigned int* rp = ((const unsigned int*)g_w1h) + (size_t)row * (NP / 2);
    unsigned int rv[32];
#pragma unroll
    for (int i = 0; i < 32; i++) rv[i] = rp[i * 32 + lane];

    float bv = -FLT_MAX; int bi = 1 << 30;
#pragma unroll
    for (int i = 0; i < 32; i++) {
        float2 f = __half22float2(*(__half2*)&rv[i]);
        int base = (i * 32 + lane) << 1;
        if (f.x > bv) { bv = f.x; bi = base; }
        if (f.y > bv) { bv = f.y; bi = base + 1; }
    }
    int* outc = g_cand + (size_t)row * NCAND;
#pragma unroll 1
    for (int it = 0; it < NCAND; it++) {
        float wv = bv; int wi = bi;
#pragma unroll
        for (int o = 16; o; o >>= 1) {
            float ov = __shfl_xor_sync(0xffffffffu, wv, o);
            int   oi = __shfl_xor_sync(0xffffffffu, wi, o);
            if (ov > wv || (ov == wv && oi < wi)) { wv = ov; wi = oi; }
        }
        if (lane == 0) outc[it] = wi;
        if (((wi >> 1) & 31) == lane) {
            int slot = wi >> 6;
            __half2 h = *(__half2*)&rv[slot];
            if (wi & 1) h.y = __ushort_as_half((unsigned short)0xFC00);
            else        h.x = __ushort_as_half((unsigned short)0xFC00);
            rv[slot] = *(unsigned int*)&h;
            bv = -FLT_MAX; bi = 1 << 30;
#pragma unroll
            for (int i = 0; i < 32; i++) {
                float2 f = __half22float2(*(__half2*)&rv[i]);
                int base = (i * 32 + lane) << 1;
                if (f.x > bv) { bv = f.x; bi = base; }
                if (f.y > bv) { bv = f.y; bi = base + 1; }
            }
        }
    }
}

// ---------------------------------------------------------------------------
// 3x3 inverse (adjugate) applied to a vector.
// ---------------------------------------------------------------------------
__device__ __forceinline__ void inv3_apply(const float* __restrict__ M,
                                           const float* __restrict__ v,
                                           float* __restrict__ o) {
    float a = M[0], b = M[1], c = M[2];
    float d = M[3], e = M[4], f = M[5];
    float g = M[6], h = M[7], i = M[8];
    float A  = e * i - f * h;
    float Bc = -(d * i - f * g);
    float Cc = d * h - e * g;
    float det = a * A + b * Bc + c * Cc;
    float id = 1.0f / det;
    float i00 = A * id,  i01 = -(b * i - c * h) * id, i02 = (b * f - c * e) * id;
    float i10 = Bc * id, i11 = (a * i - c * g) * id,  i12 = -(a * f - c * d) * id;
    float i20 = Cc * id, i21 = -(a * h - b * g) * id, i22 = (a * e - b * d) * id;
    o[0] = i00 * v[0] + i01 * v[1] + i02 * v[2];
    o[1] = i10 * v[0] + i11 * v[1] + i12 * v[2];
    o[2] = i20 * v[0] + i21 * v[1] + i22 * v[2];
}

// ---------------------------------------------------------------------------
// Fused: EXACT rescore of 32 candidates (bit-identical to the validated R1
// GEMM arithmetic: once-rounded ffp*invp / ffq*invq, strictly sequential fmaf
// over d), bitonic sort (desc value, asc index), idx output, then avg/max
// pool + refine linear + inv(R1),inv(R2) rotate-back + mask + add q.
// Candidate rows staged with stride 513 -> conflict-free column AND row access.
// ---------------------------------------------------------------------------
#define FSTRIDE 513
#define SM_SFQ   (32 * FSTRIDE * 4)            // 65664
#define SM_CI    (SM_SFQ + 2048)
#define SM_SSEL  (SM_CI + 128)
#define SM_WRED  (SM_SSEL + 64)
#define SM_FINAL (SM_WRED + 96)

__global__ __launch_bounds__(256) void k_final(
    const float* __restrict__ ffp, const float* __restrict__ ffq,
    const float* __restrict__ R1,  const float* __restrict__ R2,
    const int*   __restrict__ cen, const float* __restrict__ W,
    const float* __restrict__ bvec, const float* __restrict__ q,
    float* __restrict__ out)
{
    extern __shared__ char sm[];
    float* sfeat = (float*)sm;                 // [32][513] raw ffp rows
    float* sfq   = (float*)(sm + SM_SFQ);      // normalized fq (fp32, once-rounded)
    int*   ci    = (int*)(sm + SM_CI);
    int*   ssel  = (int*)(sm + SM_SSEL);
    float* wred  = (float*)(sm + SM_WRED);

    const int pt = blockIdx.x, b = pt >> 11;
    const int tid = threadIdx.x, lane = tid & 31, wid = tid >> 5;

    if (tid < NCAND) ci[tid] = g_cand[(size_t)pt * NCAND + tid];
    __syncthreads();

    const float* fpb = ffp + (size_t)b * NP * ND;
    const float* fqr = ffq + (size_t)pt * ND;

    // gather 32 candidate rows (raw ffp) into smem, stride 513
#pragma unroll
    for (int i = 0; i < 64; i++) {
        int id = tid + i * 256;
        int c = id >> 9, f = id & 511;
        sfeat[c * FSTRIDE + f] = fpb[(size_t)ci[c] * ND + f];
    }
    float invq = g_nq[pt];
#pragma unroll
    for (int i = 0; i < 2; i++) { int d = tid + i * 256; sfq[d] = fqr[d] * invq; }
    __syncthreads();

    // warp 0: exact sequential rescore, one candidate per lane, then sort.
    if (wid == 0) {
        float invp = g_np[b * NP + ci[lane]];
        const float* fr = sfeat + lane * FSTRIDE;
        float acc = 0.f;
#pragma unroll 8
        for (int d = 0; d < ND; d++) {
            float t = fr[d] * invp;            // once-rounded normalized fp elem
            acc = fmaf(t, sfq[d], acc);        // strictly sequential, fused
        }
        unsigned int u = __float_as_uint(acc);
        unsigned int ou = (u & 0x80000000u) ? ~u : (u | 0x80000000u);
        unsigned long long key =
            ((unsigned long long)(~ou) << 32) | (unsigned)((ci[lane] << 5) | lane);
#pragma unroll
        for (int k = 2; k <= 32; k <<= 1) {
#pragma unroll
            for (int j = k >> 1; j > 0; j >>= 1) {
                unsigned long long o = __shfl_xor_sync(0xffffffffu, key, j);
                bool dirUp = ((lane & k) == 0);
                bool lower = ((lane & j) == 0);
                unsigned long long mn = (key < o) ? key : o;
                unsigned long long mx = (key < o) ? o : key;
                key = (lower == dirUp) ? mn : mx;
            }
        }
        if (lane < NK) {
            ssel[lane] = (int)(key & 31u);
            int idx = (int)((key >> 5) & 2047u);
            out[3 * NB * NP * 3 + pt * NK + lane] = (float)idx;
        }
    }
    __syncthreads();

    // pool (avg, max over the 16 winners) + refine linear
    float pv0 = 0.f, pv1 = 0.f, pv2 = 0.f;
#pragma unroll
    for (int rr = 0; rr < 2; rr++) {
        int d = tid + rr * 256;
        float s = 0.f, mx = -FLT_MAX;
#pragma unroll
        for (int k = 0; k < NK; k++) {
            float v = sfeat[ssel[k] * FSTRIDE + d];
            s += v;
            mx = fmaxf(mx, v);
        }
        float avg = s * (1.0f / 16.0f);
        float fv  = fqr[d];
        pv0 += W[d] * fv        + W[512 + d] * avg  + W[1024 + d] * mx;
        pv1 += W[1536 + d] * fv + W[2048 + d] * avg + W[2560 + d] * mx;
        pv2 += W[3072 + d] * fv + W[3584 + d] * avg + W[4096 + d] * mx;
    }
#pragma unroll
    for (int o = 16; o; o >>= 1) {
        pv0 += __shfl_xor_sync(0xffffffffu, pv0, o);
        pv1 += __shfl_xor_sync(0xffffffffu, pv1, o);
        pv2 += __shfl_xor_sync(0xffffffffu, pv2, o);
    }
    if (lane == 0) { wred[wid] = pv0; wred[8 + wid] = pv1; wred[16 + wid] = pv2; }
    __syncthreads();

    if (tid == 0) {
        float v0 = bvec[0], v1 = bvec[1], v2 = bvec[2];
#pragma unroll
        for (int i = 0; i < 8; i++) { v0 += wred[i]; v1 += wred[8 + i]; v2 += wred[16 + i]; }
        float vin[3] = {v0, v1, v2}, t1[3], t2[3];
        inv3_apply(R1 + (size_t)pt * 9, vin, t1);
        inv3_apply(R2 + (size_t)pt * 9, t1, t2);
        float m = (cen[pt] >= NP) ? 1.0f : 0.0f;
#pragma unroll
        for (int j = 0; j < 3; j++) {
            float qr = q[pt * 3 + j] + t2[j] * m;
            out[49152 + pt * 3 + j] = qr;
            out[98304 + pt * 3 + j] = qr;
        }
    }
}

// ---------------------------------------------------------------------------
// Launch. Inputs: p, q, ffp, ffq, R1, R2, centroids, W, b
// Output: concat(q, q_refine, q_refine, idx) as f32, 409600 elems.
// ---------------------------------------------------------------------------
extern "C" void kernel_launch(void* const* d_in, const int* in_sizes, int n_in,
                              void* d_out, int out_size) {
    const float* q   = (const float*)d_in[1];
    const float* ffp = (const float*)d_in[2];
    const float* ffq = (const float*)d_in[3];
    const float* R1  = (const float*)d_in[4];
    const float* R2  = (const float*)d_in[5];
    const int*   cen = (const int*)d_in[6];
    const float* W   = (const float*)d_in[7];
    const float* bb  = (const float*)d_in[8];
    float* out = (float*)d_out;

    cudaFuncSetAttribute(k_gemm_hmma, cudaFuncAttributeMaxDynamicSharedMemorySize, 65536);
    cudaFuncSetAttribute(k_final,     cudaFuncAttributeMaxDynamicSharedMemorySize, SM_FINAL);

    __half* d_fph; cudaGetSymbolAddress((void**)&d_fph, g_fph);
    __half* d_fqh; cudaGetSymbolAddress((void**)&d_fqh, g_fqh);
    float*  d_gnp; cudaGetSymbolAddress((void**)&d_gnp, g_np);
    float*  d_gnq; cudaGetSymbolAddress((void**)&d_gnq, g_nq);

    k_normalize<<<NB * NP / 8, 256>>>(ffp, d_fph, d_gnp);
    k_normalize<<<NB * NP / 8, 256>>>(ffq, d_fqh, d_gnq);

    dim3 gg(NP / BN, NP / BM, NB);            // (16, 16, 8)
    k_gemm_hmma<<<gg, 256, 65536>>>();

    k_cand<<<NB * NP / 8, 256>>>();

    k_final<<<NB * NP, 256, SM_FINAL>>>(ffp, ffq, R1, R2, cen, W, bb, q, out);

    cudaMemcpyAsync(out, q, (size_t)NB * NP * 3 * sizeof(float),
                    cudaMemcpyDeviceToDevice);
}

// round 6
// speedup vs baseline: 2.1176x; 1.0964x over previous
#include <cuda_runtime.h>
#include <cuda_fp16.h>
#include <float.h>
#include <math.h>
#include <stdint.h>

#define NB 8
#define NP 2048
#define ND 512
#define NK 16
#define NCAND 32

// ---------------- device scratch (no allocations allowed) -------------------
__device__ __half g_fqh[(size_t)NB * NP * ND];        // normalized ffq, fp16
__device__ __half g_fph[(size_t)NB * NP * ND];        // normalized ffp, fp16
__device__ float  g_nq[NB * NP];                      // 1/(||ffq||+eps)
__device__ float  g_np[NB * NP];                      // 1/(||ffp||+eps)
__device__ __half g_w1h[(size_t)NB * NP * NP];        // similarity, fp16
__device__ int    g_cand[NB * NP * NCAND];            // top-32 candidates per row

// ---------------- helpers ---------------------------------------------------
__device__ __forceinline__ uint32_t smem_u32(const void* p) {
    uint32_t a;
    asm("{ .reg .u64 t; cvta.to.shared.u64 t, %1; cvt.u32.u64 %0, t; }" : "=r"(a) : "l"(p));
    return a;
}
#define SWZ(off) ((off) ^ (((off) >> 3) & 0x70))

__device__ __forceinline__ void cp16(uint32_t dst, const void* src) {
    asm volatile("cp.async.cg.shared.global [%0], [%1], 16;" :: "r"(dst), "l"(src));
}
#define CP_COMMIT() asm volatile("cp.async.commit_group;" ::: "memory")
#define CP_WAIT(n)  asm volatile("cp.async.wait_group %0;" :: "n"(n) : "memory")

#define LDSM4(r, addr)                                                          \
    asm volatile("ldmatrix.sync.aligned.m8n8.x4.shared.b16 {%0,%1,%2,%3}, [%4];" \
        : "=r"((r)[0]), "=r"((r)[1]), "=r"((r)[2]), "=r"((r)[3]) : "r"(addr))

__device__ __forceinline__ void mma16816(float* d, const uint32_t* a,
                                         uint32_t b0, uint32_t b1) {
    asm volatile(
        "mma.sync.aligned.m16n8k16.row.col.f32.f16.f16.f32 "
        "{%0,%1,%2,%3},{%4,%5,%6,%7},{%8,%9},{%0,%1,%2,%3};"
        : "+f"(d[0]), "+f"(d[1]), "+f"(d[2]), "+f"(d[3])
        : "r"(a[0]), "r"(a[1]), "r"(a[2]), "r"(a[3]), "r"(b0), "r"(b1));
}

// ---------------------------------------------------------------------------
// Normalize rows by (L2 + 1e-8) for both tensors in one launch (blockIdx.y
// selects ffp/ffq). Norm reduction = exact validated R1 arithmetic.
// ---------------------------------------------------------------------------
__global__ void k_normalize2(const float* __restrict__ srcp, __half* __restrict__ dstp,
                             float* __restrict__ invnp,
                             const float* __restrict__ srcq, __half* __restrict__ dstq,
                             float* __restrict__ invnq) {
    const float* src = blockIdx.y ? srcq : srcp;
    __half* dst = blockIdx.y ? dstq : dstp;
    float* invn = blockIdx.y ? invnq : invnp;
    int row  = blockIdx.x * 8 + (threadIdx.x >> 5);
    int lane = threadIdx.x & 31;
    const float* s = src + (size_t)row * ND;
    float ss = 0.f;
    for (int d = lane; d < ND; d += 32) { float v = s[d]; ss = fmaf(v, v, ss); }
#pragma unroll
    for (int o = 16; o; o >>= 1) ss += __shfl_xor_sync(0xffffffffu, ss, o);
    float inv = 1.0f / (sqrtf(ss) + 1e-8f);
    if (lane == 0) invn[row] = inv;
    const float2* s2 = (const float2*)s;
    __half2* d2 = (__half2*)(dst + (size_t)row * ND);
#pragma unroll
    for (int i = 0; i < 8; i++) {
        float2 v = s2[lane + 32 * i];
        d2[lane + 32 * i] = __floats2half2_rn(v.x * inv, v.y * inv);
    }
}

// ---------------------------------------------------------------------------
// HMMA fp16 GEMM: w1[b] = fq[b] @ fp[b]^T -> fp16.
// 128x128 tile, BK=64, cp.async double buffer, 8 warps in 4(M) x 2(N),
// warp tile 32x64, mma.m16n8k16, fp32 accumulate.
// ---------------------------------------------------------------------------
#define BM 128
#define BN 128
#define BK 64

__global__ __launch_bounds__(256) void k_gemm_hmma() {
    extern __shared__ char sm[];
    const uint32_t sb = smem_u32(sm);
    const int tid = threadIdx.x, lane = tid & 31, wid = tid >> 5;
    const int wm = wid & 3, wn = wid >> 2;
    const int bz = blockIdx.z;
    const __half* Ag = g_fqh + ((size_t)bz * NP + blockIdx.y * BM) * ND;
    const __half* Bg = g_fph + ((size_t)bz * NP + blockIdx.x * BN) * ND;

    auto load = [&](int kc, int buf) {
        uint32_t abase = sb + buf * 32768;
        const __half* ap = Ag + kc * BK;
#pragma unroll
        for (int i = 0; i < 4; i++) {
            int id = tid + i * 256;
            int r = id >> 3, c = id & 7;
            cp16(abase + SWZ(r * 128 + c * 16), ap + (size_t)r * ND + c * 8);
        }
        uint32_t bbase = abase + 16384;
        const __half* bp = Bg + kc * BK;
#pragma unroll
        for (int i = 0; i < 4; i++) {
            int id = tid + i * 256;
            int r = id >> 3, c = id & 7;
            cp16(bbase + SWZ(r * 128 + c * 16), bp + (size_t)r * ND + c * 8);
        }
    };

    float acc[2][8][4];
#pragma unroll
    for (int t = 0; t < 2; t++)
#pragma unroll
        for (int n = 0; n < 8; n++)
#pragma unroll
            for (int i = 0; i < 4; i++) acc[t][n][i] = 0.f;

    load(0, 0);
    CP_COMMIT();

    const int lrow = lane & 15;
    const int lk16 = (lane >> 4) * 16;

#pragma unroll 1
    for (int c = 0; c < 8; c++) {
        int buf = c & 1;
        if (c < 7) { load(c + 1, buf ^ 1); CP_COMMIT(); CP_WAIT(1); }
        else       { CP_WAIT(0); }
        __syncthreads();
        uint32_t Asb = sb + buf * 32768;
        uint32_t Bsb = Asb + 16384;
#pragma unroll
        for (int ks = 0; ks < 4; ks++) {
            uint32_t a[2][4];
#pragma unroll
            for (int t = 0; t < 2; t++) {
                int row = wm * 32 + t * 16 + lrow;
                uint32_t off = (uint32_t)(row * 128 + ks * 32 + lk16) ^ ((row & 7) << 4);
                LDSM4(a[t], Asb + off);
            }
            uint32_t bfr[4][4];
#pragma unroll
            for (int j = 0; j < 4; j++) {
                int row = wn * 64 + j * 16 + lrow;
                uint32_t off = (uint32_t)(row * 128 + ks * 32 + lk16) ^ ((row & 7) << 4);
                LDSM4(bfr[j], Bsb + off);
            }
#pragma unroll
            for (int t = 0; t < 2; t++)
#pragma unroll
                for (int n8 = 0; n8 < 8; n8++) {
                    int j = n8 >> 1, hi = n8 & 1;
                    mma16816(acc[t][n8], a[t], bfr[j][hi ? 1 : 0], bfr[j][hi ? 3 : 2]);
                }
        }
        __syncthreads();
    }

    const int q0 = blockIdx.y * BM, p0 = blockIdx.x * BN;
#pragma unroll
    for (int t = 0; t < 2; t++)
#pragma unroll
        for (int n8 = 0; n8 < 8; n8++) {
            int m = q0 + wm * 32 + t * 16 + (lane >> 2);
            int n = p0 + wn * 64 + n8 * 8 + (lane & 3) * 2;
            size_t base = ((size_t)bz * NP + m) * NP + n;
            *(__half2*)(g_w1h + base) =
                __floats2half2_rn(acc[t][n8][0], acc[t][n8][1]);
            *(__half2*)(g_w1h + base + (size_t)8 * NP) =
                __floats2half2_rn(acc[t][n8][2], acc[t][n8][3]);
        }
}

// ---------------------------------------------------------------------------
// Per-row top-32 candidates from fp16 w1. One warp per row; row register-
// resident (32 x half2 per lane). Per-lane sorted top-4 buffer; global
// selection reduces over lane heads; exact rescan fallback on buffer
// exhaustion. Ordering identical to full iterative argmax (desc val, asc idx).
// ---------------------------------------------------------------------------
__global__ __launch_bounds__(256) void k_cand() {
    int row  = blockIdx.x * 8 + (threadIdx.x >> 5);
    int lane = threadIdx.x & 31;
    const unsigned int* rp = ((const unsigned int*)g_w1h) + (size_t)row * (NP / 2);
    unsigned int rv[32];
#pragma unroll
    for (int i = 0; i < 32; i++) rv[i] = rp[i * 32 + lane];

    float bv0 = -FLT_MAX, bv1 = -FLT_MAX, bv2 = -FLT_MAX, bv3 = -FLT_MAX;
    int   bi0 = 1 << 30,  bi1 = 1 << 30,  bi2 = 1 << 30,  bi3 = 1 << 30;

    auto ins = [&](float v, int id) {
        if (v > bv3) {
            if (v > bv1) {
                if (v > bv0) {
                    bv3 = bv2; bi3 = bi2; bv2 = bv1; bi2 = bi1;
                    bv1 = bv0; bi1 = bi0; bv0 = v;  bi0 = id;
                } else {
                    bv3 = bv2; bi3 = bi2; bv2 = bv1; bi2 = bi1;
                    bv1 = v;  bi1 = id;
                }
            } else {
                if (v > bv2) { bv3 = bv2; bi3 = bi2; bv2 = v; bi2 = id; }
                else         { bv3 = v;  bi3 = id; }
            }
        }
    };
    auto build = [&]() {
        bv0 = bv1 = bv2 = bv3 = -FLT_MAX;
        bi0 = bi1 = bi2 = bi3 = 1 << 30;
#pragma unroll
        for (int i = 0; i < 32; i++) {
            float2 f = __half22float2(*(__half2*)&rv[i]);
            int base = (i * 32 + lane) << 1;
            ins(f.x, base);
            ins(f.y, base + 1);
        }
    };
    build();

    int* outc = g_cand + (size_t)row * NCAND;
#pragma unroll 1
    for (int it = 0; it < NCAND; it++) {
        float wv = bv0; int wi = bi0;
#pragma unroll
        for (int o = 16; o; o >>= 1) {
            float ov = __shfl_xor_sync(0xffffffffu, wv, o);
            int   oi = __shfl_xor_sync(0xffffffffu, wi, o);
            if (ov > wv || (ov == wv && oi < wi)) { wv = ov; wi = oi; }
        }
        if (lane == 0) outc[it] = wi;
        if (bi0 == wi) {                       // unique col indices -> winner lane
            int slot = wi >> 6;                // mark consumed in rv
            __half2 h = *(__half2*)&rv[slot];
            if (wi & 1) h.y = __ushort_as_half((unsigned short)0xFC00);
            else        h.x = __ushort_as_half((unsigned short)0xFC00);
            rv[slot] = *(unsigned int*)&h;
            bv0 = bv1; bi0 = bi1; bv1 = bv2; bi1 = bi2;
            bv2 = bv3; bi2 = bi3; bv3 = -FLT_MAX; bi3 = 1 << 30;
            if (bv0 == -FLT_MAX) build();      // exact fallback (rare)
        }
    }
}

// ---------------------------------------------------------------------------
// 3x3 inverse (adjugate) applied to a vector.
// ---------------------------------------------------------------------------
__device__ __forceinline__ void inv3_apply(const float* __restrict__ M,
                                           const float* __restrict__ v,
                                           float* __restrict__ o) {
    float a = M[0], b = M[1], c = M[2];
    float d = M[3], e = M[4], f = M[5];
    float g = M[6], h = M[7], i = M[8];
    float A  = e * i - f * h;
    float Bc = -(d * i - f * g);
    float Cc = d * h - e * g;
    float det = a * A + b * Bc + c * Cc;
    float id = 1.0f / det;
    float i00 = A * id,  i01 = -(b * i - c * h) * id, i02 = (b * f - c * e) * id;
    float i10 = Bc * id, i11 = (a * i - c * g) * id,  i12 = -(a * f - c * d) * id;
    float i20 = Cc * id, i21 = -(a * h - b * g) * id, i22 = (a * e - b * d) * id;
    o[0] = i00 * v[0] + i01 * v[1] + i02 * v[2];
    o[1] = i10 * v[0] + i11 * v[1] + i12 * v[2];
    o[2] = i20 * v[0] + i21 * v[1] + i22 * v[2];
}

// ---------------------------------------------------------------------------
// Fused: EXACT sequential-fp32 rescore of 32 candidates, bitonic sort
// (desc value, asc index), idx output, then avg/max pool + refine linear +
// inv(R1),inv(R2) rotate-back + mask + add q.  Stride-513 smem rows are
// conflict-free for both column (rescore) and row (pool) access.
// ---------------------------------------------------------------------------
#define FSTRIDE 513
#define SM_SFQ   (32 * FSTRIDE * 4)            // 65664
#define SM_CI    (SM_SFQ + 2048)
#define SM_SSEL  (SM_CI + 128)
#define SM_WRED  (SM_SSEL + 64)
#define SM_FINAL (SM_WRED + 96)

__global__ __launch_bounds__(256) void k_final(
    const float* __restrict__ ffp, const float* __restrict__ ffq,
    const float* __restrict__ R1,  const float* __restrict__ R2,
    const int*   __restrict__ cen, const float* __restrict__ W,
    const float* __restrict__ bvec, const float* __restrict__ q,
    float* __restrict__ out)
{
    extern __shared__ char sm[];
    float* sfeat = (float*)sm;                 // [32][513] raw ffp rows
    float* sfq   = (float*)(sm + SM_SFQ);      // normalized fq (fp32, once-rounded)
    int*   ci    = (int*)(sm + SM_CI);
    int*   ssel  = (int*)(sm + SM_SSEL);
    float* wred  = (float*)(sm + SM_WRED);

    const int pt = blockIdx.x, b = pt >> 11;
    const int tid = threadIdx.x, lane = tid & 31, wid = tid >> 5;

    if (tid < NCAND) ci[tid] = g_cand[(size_t)pt * NCAND + tid];
    __syncthreads();

    const float* fpb = ffp + (size_t)b * NP * ND;
    const float* fqr = ffq + (size_t)pt * ND;

    // gather 32 candidate rows (raw ffp) into smem, float4 loads, stride 513
#pragma unroll
    for (int i = 0; i < 16; i++) {
        int id = tid + i * 256;
        int c = id >> 7, f = (id & 127) << 2;
        float4 v = *(const float4*)(fpb + (size_t)ci[c] * ND + f);
        float* dst = sfeat + c * FSTRIDE + f;
        dst[0] = v.x; dst[1] = v.y; dst[2] = v.z; dst[3] = v.w;
    }
    float invq = g_nq[pt];
#pragma unroll
    for (int i = 0; i < 2; i++) { int d = tid + i * 256; sfq[d] = fqr[d] * invq; }
    __syncthreads();

    // warp 0: exact sequential rescore, one candidate per lane, then sort.
    if (wid == 0) {
        float invp = g_np[b * NP + ci[lane]];
        const float* fr = sfeat + lane * FSTRIDE;
        float acc = 0.f;
#pragma unroll 8
        for (int d = 0; d < ND; d++) {
            float t = fr[d] * invp;            // once-rounded normalized fp elem
            acc = fmaf(t, sfq[d], acc);        // strictly sequential, fused
        }
        unsigned int u = __float_as_uint(acc);
        unsigned int ou = (u & 0x80000000u) ? ~u : (u | 0x80000000u);
        unsigned long long key =
            ((unsigned long long)(~ou) << 32) | (unsigned)((ci[lane] << 5) | lane);
#pragma unroll
        for (int k = 2; k <= 32; k <<= 1) {
#pragma unroll
            for (int j = k >> 1; j > 0; j >>= 1) {
                unsigned long long o = __shfl_xor_sync(0xffffffffu, key, j);
                bool dirUp = ((lane & k) == 0);
                bool lower = ((lane & j) == 0);
                unsigned long long mn = (key < o) ? key : o;
                unsigned long long mx = (key < o) ? o : key;
                key = (lower == dirUp) ? mn : mx;
            }
        }
        if (lane < NK) {
            ssel[lane] = (int)(key & 31u);
            int idx = (int)((key >> 5) & 2047u);
            out[3 * NB * NP * 3 + pt * NK + lane] = (float)idx;
        }
    }
    __syncthreads();

    // pool (avg, max over the 16 winners) + refine linear
    float pv0 = 0.f, pv1 = 0.f, pv2 = 0.f;
#pragma unroll
    for (int rr = 0; rr < 2; rr++) {
        int d = tid + rr * 256;
        float s = 0.f, mx = -FLT_MAX;
#pragma unroll
        for (int k = 0; k < NK; k++) {
            float v = sfeat[ssel[k] * FSTRIDE + d];
            s += v;
            mx = fmaxf(mx, v);
        }
        float avg = s * (1.0f / 16.0f);
        float fv  = fqr[d];
        pv0 += W[d] * fv        + W[512 + d] * avg  + W[1024 + d] * mx;
        pv1 += W[1536 + d] * fv + W[2048 + d] * avg + W[2560 + d] * mx;
        pv2 += W[3072 + d] * fv + W[3584 + d] * avg + W[4096 + d] * mx;
    }
#pragma unroll
    for (int o = 16; o; o >>= 1) {
        pv0 += __shfl_xor_sync(0xffffffffu, pv0, o);
        pv1 += __shfl_xor_sync(0xffffffffu, pv1, o);
        pv2 += __shfl_xor_sync(0xffffffffu, pv2, o);
    }
    if (lane == 0) { wred[wid] = pv0; wred[8 + wid] = pv1; wred[16 + wid] = pv2; }
    __syncthreads();

    if (tid == 0) {
        float v0 = bvec[0], v1 = bvec[1], v2 = bvec[2];
#pragma unroll
        for (int i = 0; i < 8; i++) { v0 += wred[i]; v1 += wred[8 + i]; v2 += wred[16 + i]; }
        float vin[3] = {v0, v1, v2}, t1[3], t2[3];
        inv3_apply(R1 + (size_t)pt * 9, vin, t1);
        inv3_apply(R2 + (size_t)pt * 9, t1, t2);
        float m = (cen[pt] >= NP) ? 1.0f : 0.0f;
#pragma unroll
        for (int j = 0; j < 3; j++) {
            float qr = q[pt * 3 + j] + t2[j] * m;
            out[49152 + pt * 3 + j] = qr;
            out[98304 + pt * 3 + j] = qr;
        }
    }
}

// ---------------------------------------------------------------------------
// Launch. Inputs: p, q, ffp, ffq, R1, R2, centroids, W, b
// Output: concat(q, q_refine, q_refine, idx) as f32, 409600 elems.
// ---------------------------------------------------------------------------
extern "C" void kernel_launch(void* const* d_in, const int* in_sizes, int n_in,
                              void* d_out, int out_size) {
    const float* q   = (const float*)d_in[1];
    const float* ffp = (const float*)d_in[2];
    const float* ffq = (const float*)d_in[3];
    const float* R1  = (const float*)d_in[4];
    const float* R2  = (const float*)d_in[5];
    const int*   cen = (const int*)d_in[6];
    const float* W   = (const float*)d_in[7];
    const float* bb  = (const float*)d_in[8];
    float* out = (float*)d_out;

    cudaFuncSetAttribute(k_gemm_hmma, cudaFuncAttributeMaxDynamicSharedMemorySize, 65536);
    cudaFuncSetAttribute(k_final,     cudaFuncAttributeMaxDynamicSharedMemorySize, SM_FINAL);

    __half* d_fph; cudaGetSymbolAddress((void**)&d_fph, g_fph);
    __half* d_fqh; cudaGetSymbolAddress((void**)&d_fqh, g_fqh);
    float*  d_gnp; cudaGetSymbolAddress((void**)&d_gnp, g_np);
    float*  d_gnq; cudaGetSymbolAddress((void**)&d_gnq, g_nq);

    dim3 gn(NB * NP / 8, 2);
    k_normalize2<<<gn, 256>>>(ffp, d_fph, d_gnp, ffq, d_fqh, d_gnq);

    dim3 gg(NP / BN, NP / BM, NB);            // (16, 16, 8)
    k_gemm_hmma<<<gg, 256, 65536>>>();

    k_cand<<<NB * NP / 8, 256>>>();

    k_final<<<NB * NP, 256, SM_FINAL>>>(ffp, ffq, R1, R2, cen, W, bb, q, out);

    cudaMemcpyAsync(out, q, (size_t)NB * NP * 3 * sizeof(float),
                    cudaMemcpyDeviceToDevice);
}

// round 11
// speedup vs baseline: 2.4673x; 1.1652x over previous
#include <cuda_runtime.h>
#include <cuda_fp16.h>
#include <float.h>
#include <math.h>
#include <stdint.h>

#define NB 8
#define NP 2048
#define ND 512
#define NK 16
#define NCAND 32

// ---------------- device scratch (no allocations allowed) -------------------
__device__ __half g_fqh[(size_t)NB * NP * ND];        // normalized ffq, fp16
__device__ __half g_fph[(size_t)NB * NP * ND];        // normalized ffp, fp16
__device__ float  g_nq[NB * NP];                      // 1/(||ffq||+eps)
__device__ float  g_np[NB * NP];                      // 1/(||ffp||+eps)
__device__ __half g_w1h[(size_t)NB * NP * NP];        // similarity, fp16
__device__ int    g_cand[NB * NP * NCAND];            // top-32 candidates per row
__device__ int    g_sel[NB * NP * NK];                // final top-16 (global idx)

// ---------------- helpers ---------------------------------------------------
__device__ __forceinline__ uint32_t smem_u32(const void* p) {
    uint32_t a;
    asm("{ .reg .u64 t; cvta.to.shared.u64 t, %1; cvt.u32.u64 %0, t; }" : "=r"(a) : "l"(p));
    return a;
}
#define SWZ(off) ((off) ^ (((off) >> 3) & 0x70))

__device__ __forceinline__ void cp16(uint32_t dst, const void* src) {
    asm volatile("cp.async.cg.shared.global [%0], [%1], 16;" :: "r"(dst), "l"(src));
}
#define CP_COMMIT() asm volatile("cp.async.commit_group;" ::: "memory")
#define CP_WAIT(n)  asm volatile("cp.async.wait_group %0;" :: "n"(n) : "memory")

#define LDSM4(r, addr)                                                          \
    asm volatile("ldmatrix.sync.aligned.m8n8.x4.shared.b16 {%0,%1,%2,%3}, [%4];" \
        : "=r"((r)[0]), "=r"((r)[1]), "=r"((r)[2]), "=r"((r)[3]) : "r"(addr))

__device__ __forceinline__ void mma16816(float* d, const uint32_t* a,
                                         uint32_t b0, uint32_t b1) {
    asm volatile(
        "mma.sync.aligned.m16n8k16.row.col.f32.f16.f16.f32 "
        "{%0,%1,%2,%3},{%4,%5,%6,%7},{%8,%9},{%0,%1,%2,%3};"
        : "+f"(d[0]), "+f"(d[1]), "+f"(d[2]), "+f"(d[3])
        : "r"(a[0]), "r"(a[1]), "r"(a[2]), "r"(a[3]), "r"(b0), "r"(b1));
}

// ---------------------------------------------------------------------------
// Normalize rows by (L2 + 1e-8) for both tensors in one launch (blockIdx.y
// selects ffp/ffq). Norm reduction = exact validated R1 arithmetic.
// ---------------------------------------------------------------------------
__global__ void k_normalize2(const float* __restrict__ srcp, __half* __restrict__ dstp,
                             float* __restrict__ invnp,
                             const float* __restrict__ srcq, __half* __restrict__ dstq,
                             float* __restrict__ invnq) {
    const float* src = blockIdx.y ? srcq : srcp;
    __half* dst = blockIdx.y ? dstq : dstp;
    float* invn = blockIdx.y ? invnq : invnp;
    int row  = blockIdx.x * 8 + (threadIdx.x >> 5);
    int lane = threadIdx.x & 31;
    const float* s = src + (size_t)row * ND;
    float ss = 0.f;
    for (int d = lane; d < ND; d += 32) { float v = s[d]; ss = fmaf(v, v, ss); }
#pragma unroll
    for (int o = 16; o; o >>= 1) ss += __shfl_xor_sync(0xffffffffu, ss, o);
    float inv = 1.0f / (sqrtf(ss) + 1e-8f);
    if (lane == 0) invn[row] = inv;
    const float2* s2 = (const float2*)s;
    __half2* d2 = (__half2*)(dst + (size_t)row * ND);
#pragma unroll
    for (int i = 0; i < 8; i++) {
        float2 v = s2[lane + 32 * i];
        d2[lane + 32 * i] = __floats2half2_rn(v.x * inv, v.y * inv);
    }
}

// ---------------------------------------------------------------------------
// HMMA fp16 GEMM: w1[b] = fq[b] @ fp[b]^T -> fp16.
// 128x128 tile, BK=64, cp.async double buffer, 8 warps in 4(M) x 2(N),
// warp tile 32x64, mma.m16n8k16, fp32 accumulate.
// ---------------------------------------------------------------------------
#define BM 128
#define BN 128
#define BK 64

__global__ __launch_bounds__(256) void k_gemm_hmma() {
    extern __shared__ char sm[];
    const uint32_t sb = smem_u32(sm);
    const int tid = threadIdx.x, lane = tid & 31, wid = tid >> 5;
    const int wm = wid & 3, wn = wid >> 2;
    const int bz = blockIdx.z;
    const __half* Ag = g_fqh + ((size_t)bz * NP + blockIdx.y * BM) * ND;
    const __half* Bg = g_fph + ((size_t)bz * NP + blockIdx.x * BN) * ND;

    auto load = [&](int kc, int buf) {
        uint32_t abase = sb + buf * 32768;
        const __half* ap = Ag + kc * BK;
#pragma unroll
        for (int i = 0; i < 4; i++) {
            int id = tid + i * 256;
            int r = id >> 3, c = id & 7;
            cp16(abase + SWZ(r * 128 + c * 16), ap + (size_t)r * ND + c * 8);
        }
        uint32_t bbase = abase + 16384;
        const __half* bp = Bg + kc * BK;
#pragma unroll
        for (int i = 0; i < 4; i++) {
            int id = tid + i * 256;
            int r = id >> 3, c = id & 7;
            cp16(bbase + SWZ(r * 128 + c * 16), bp + (size_t)r * ND + c * 8);
        }
    };

    float acc[2][8][4];
#pragma unroll
    for (int t = 0; t < 2; t++)
#pragma unroll
        for (int n = 0; n < 8; n++)
#pragma unroll
            for (int i = 0; i < 4; i++) acc[t][n][i] = 0.f;

    load(0, 0);
    CP_COMMIT();

    const int lrow = lane & 15;
    const int lk16 = (lane >> 4) * 16;

#pragma unroll 1
    for (int c = 0; c < 8; c++) {
        int buf = c & 1;
        if (c < 7) { load(c + 1, buf ^ 1); CP_COMMIT(); CP_WAIT(1); }
        else       { CP_WAIT(0); }
        __syncthreads();
        uint32_t Asb = sb + buf * 32768;
        uint32_t Bsb = Asb + 16384;
#pragma unroll
        for (int ks = 0; ks < 4; ks++) {
            uint32_t a[2][4];
#pragma unroll
            for (int t = 0; t < 2; t++) {
                int row = wm * 32 + t * 16 + lrow;
                uint32_t off = (uint32_t)(row * 128 + ks * 32 + lk16) ^ ((row & 7) << 4);
                LDSM4(a[t], Asb + off);
            }
            uint32_t bfr[4][4];
#pragma unroll
            for (int j = 0; j < 4; j++) {
                int row = wn * 64 + j * 16 + lrow;
                uint32_t off = (uint32_t)(row * 128 + ks * 32 + lk16) ^ ((row & 7) << 4);
                LDSM4(bfr[j], Bsb + off);
            }
#pragma unroll
            for (int t = 0; t < 2; t++)
#pragma unroll
                for (int n8 = 0; n8 < 8; n8++) {
                    int j = n8 >> 1, hi = n8 & 1;
                    mma16816(acc[t][n8], a[t], bfr[j][hi ? 1 : 0], bfr[j][hi ? 3 : 2]);
                }
        }
        __syncthreads();
    }

    const int q0 = blockIdx.y * BM, p0 = blockIdx.x * BN;
#pragma unroll
    for (int t = 0; t < 2; t++)
#pragma unroll
        for (int n8 = 0; n8 < 8; n8++) {
            int m = q0 + wm * 32 + t * 16 + (lane >> 2);
            int n = p0 + wn * 64 + n8 * 8 + (lane & 3) * 2;
            size_t base = ((size_t)bz * NP + m) * NP + n;
            *(__half2*)(g_w1h + base) =
                __floats2half2_rn(acc[t][n8][0], acc[t][n8][1]);
            *(__half2*)(g_w1h + base + (size_t)8 * NP) =
                __floats2half2_rn(acc[t][n8][2], acc[t][n8][3]);
        }
}

// ---------------------------------------------------------------------------
// Per-row top-32 candidates from fp16 w1. One warp per row; row register-
// resident. Per-lane sorted top-4 buffer; butterfly over lane heads; exact
// rescan fallback on buffer exhaustion.
// ---------------------------------------------------------------------------
__global__ __launch_bounds__(256) void k_cand() {
    int row  = blockIdx.x * 8 + (threadIdx.x >> 5);
    int lane = threadIdx.x & 31;
    const unsigned int* rp = ((const unsigned int*)g_w1h) + (size_t)row * (NP / 2);
    unsigned int rv[32];
#pragma unroll
    for (int i = 0; i < 32; i++) rv[i] = rp[i * 32 + lane];

    float bv0 = -FLT_MAX, bv1 = -FLT_MAX, bv2 = -FLT_MAX, bv3 = -FLT_MAX;
    int   bi0 = 1 << 30,  bi1 = 1 << 30,  bi2 = 1 << 30,  bi3 = 1 << 30;

    auto ins = [&](float v, int id) {
        if (v > bv3) {
            if (v > bv1) {
                if (v > bv0) {
                    bv3 = bv2; bi3 = bi2; bv2 = bv1; bi2 = bi1;
                    bv1 = bv0; bi1 = bi0; bv0 = v;  bi0 = id;
                } else {
                    bv3 = bv2; bi3 = bi2; bv2 = bv1; bi2 = bi1;
                    bv1 = v;  bi1 = id;
                }
            } else {
                if (v > bv2) { bv3 = bv2; bi3 = bi2; bv2 = v; bi2 = id; }
                else         { bv3 = v;  bi3 = id; }
            }
        }
    };
    auto build = [&]() {
        bv0 = bv1 = bv2 = bv3 = -FLT_MAX;
        bi0 = bi1 = bi2 = bi3 = 1 << 30;
#pragma unroll
        for (int i = 0; i < 32; i++) {
            float2 f = __half22float2(*(__half2*)&rv[i]);
            int base = (i * 32 + lane) << 1;
            ins(f.x, base);
            ins(f.y, base + 1);
        }
    };
    build();

    int* outc = g_cand + (size_t)row * NCAND;
#pragma unroll 1
    for (int it = 0; it < NCAND; it++) {
        float wv = bv0; int wi = bi0;
#pragma unroll
        for (int o = 16; o; o >>= 1) {
            float ov = __shfl_xor_sync(0xffffffffu, wv, o);
            int   oi = __shfl_xor_sync(0xffffffffu, wi, o);
            if (ov > wv || (ov == wv && oi < wi)) { wv = ov; wi = oi; }
        }
        if (lane == 0) outc[it] = wi;
        if (bi0 == wi) {
            int slot = wi >> 6;
            __half2 h = *(__half2*)&rv[slot];
            if (wi & 1) h.y = __ushort_as_half((unsigned short)0xFC00);
            else        h.x = __ushort_as_half((unsigned short)0xFC00);
            rv[slot] = *(unsigned int*)&h;
            bv0 = bv1; bi0 = bi1; bv1 = bv2; bi1 = bi2;
            bv2 = bv3; bi2 = bi3; bv3 = -FLT_MAX; bi3 = 1 << 30;
            if (bv0 == -FLT_MAX) build();
        }
    }
}

// ---------------------------------------------------------------------------
// Exact rescore + sort. One WARP per point (8 points/block). Each lane owns
// one candidate and streams its raw ffp row from L2 (float4, prefetch 1),
// running the bit-identical sequential mul->fmaf chain of the validated
// kernel. Bitonic sort (desc value, asc index); writes winner indices to
// g_sel and the float idx output.
// ---------------------------------------------------------------------------
__global__ __launch_bounds__(256) void k_rescore(
    const float* __restrict__ ffp, const float* __restrict__ ffq,
    float* __restrict__ out)
{
    __shared__ float sfq[8][ND];
    const int wid = threadIdx.x >> 5, lane = threadIdx.x & 31;
    const int pt = blockIdx.x * 8 + wid;
    const int b = pt >> 11;

    // stage normalized fq row (once-rounded fp32, same arithmetic as before)
    const float4* fq4 = (const float4*)(ffq + (size_t)pt * ND);
    float invq = g_nq[pt];
    float4* sq4 = (float4*)sfq[wid];
#pragma unroll
    for (int i = 0; i < 4; i++) {
        float4 v = fq4[lane + 32 * i];
        v.x *= invq; v.y *= invq; v.z *= invq; v.w *= invq;
        sq4[lane + 32 * i] = v;
    }
    __syncwarp();

    int ci = g_cand[(size_t)pt * NCAND + lane];
    float invp = g_np[b * NP + ci];
    const float4* fr4 = (const float4*)(ffp + ((size_t)b * NP + ci) * ND);
    const float* sq = sfq[wid];

    float acc = 0.f;
    float4 cur = __ldg(fr4);
#pragma unroll 4
    for (int d4 = 0; d4 < ND / 4; d4++) {
        float4 nxt;
        if (d4 < ND / 4 - 1) nxt = __ldg(fr4 + d4 + 1);
        int d = d4 * 4;
        acc = fmaf(cur.x * invp, sq[d + 0], acc);
        acc = fmaf(cur.y * invp, sq[d + 1], acc);
        acc = fmaf(cur.z * invp, sq[d + 2], acc);
        acc = fmaf(cur.w * invp, sq[d + 3], acc);
        cur = nxt;
    }

    unsigned int u = __float_as_uint(acc);
    unsigned int ou = (u & 0x80000000u) ? ~u : (u | 0x80000000u);
    unsigned long long key =
        ((unsigned long long)(~ou) << 32) | (unsigned)((ci << 5) | lane);
#pragma unroll
    for (int k = 2; k <= 32; k <<= 1) {
#pragma unroll
        for (int j = k >> 1; j > 0; j >>= 1) {
            unsigned long long o = __shfl_xor_sync(0xffffffffu, key, j);
            bool dirUp = ((lane & k) == 0);
            bool lower = ((lane & j) == 0);
            unsigned long long mn = (key < o) ? key : o;
            unsigned long long mx = (key < o) ? o : key;
            key = (lower == dirUp) ? mn : mx;
        }
    }
    if (lane < NK) {
        int idx = (int)((key >> 5) & 2047u);
        g_sel[pt * NK + lane] = idx;
        out[3 * NB * NP * 3 + pt * NK + lane] = (float)idx;
    }
}

// ---------------------------------------------------------------------------
// 3x3 inverse (adjugate) applied to a vector.
// ---------------------------------------------------------------------------
__device__ __forceinline__ void inv3_apply(const float* __restrict__ M,
                                           const float* __restrict__ v,
                                           float* __restrict__ o) {
    float a = M[0], b = M[1], c = M[2];
    float d = M[3], e = M[4], f = M[5];
    float g = M[6], h = M[7], i = M[8];
    float A  = e * i - f * h;
    float Bc = -(d * i - f * g);
    float Cc = d * h - e * g;
    float det = a * A + b * Bc + c * Cc;
    float id = 1.0f / det;
    float i00 = A * id,  i01 = -(b * i - c * h) * id, i02 = (b * f - c * e) * id;
    float i10 = Bc * id, i11 = (a * i - c * g) * id,  i12 = -(a * f - c * d) * id;
    float i20 = Cc * id, i21 = -(a * h - b * g) * id, i22 = (a * e - b * d) * id;
    o[0] = i00 * v[0] + i01 * v[1] + i02 * v[2];
    o[1] = i10 * v[0] + i11 * v[1] + i12 * v[2];
    o[2] = i20 * v[0] + i21 * v[1] + i22 * v[2];
}

// ---------------------------------------------------------------------------
// Pool (avg/max over the 16 winners, read straight from L2, coalesced) +
// refine linear + inv(R1),inv(R2) rotate-back + mask + add q.
// One block per point, no candidate staging -> high occupancy.
// ---------------------------------------------------------------------------
__global__ __launch_bounds__(256) void k_pool(
    const float* __restrict__ ffp, const float* __restrict__ ffq,
    const float* __restrict__ R1,  const float* __restrict__ R2,
    const int*   __restrict__ cen, const float* __restrict__ W,
    const float* __restrict__ bvec, const float* __restrict__ q,
    float* __restrict__ out)
{
    __shared__ int   ssel[NK];
    __shared__ float wred[24];
    const int pt = blockIdx.x, b = pt >> 11;
    const int tid = threadIdx.x, lane = tid & 31, wid = tid >> 5;

    if (tid < NK) ssel[tid] = g_sel[pt * NK + tid];
    __syncthreads();

    const float* fpb = ffp + (size_t)b * NP * ND;
    const float* fqr = ffq + (size_t)pt * ND;

    float pv0 = 0.f, pv1 = 0.f, pv2 = 0.f;
#pragma unroll
    for (int rr = 0; rr < 2; rr++) {
        int d = tid + rr * 256;
        float s = 0.f, mx = -FLT_MAX;
#pragma unroll
        for (int k = 0; k < NK; k++) {
            float v = __ldg(fpb + (size_t)ssel[k] * ND + d);
            s += v;
            mx = fmaxf(mx, v);
        }
        float avg = s * (1.0f / 16.0f);
        float fv  = fqr[d];
        pv0 += W[d] * fv        + W[512 + d] * avg  + W[1024 + d] * mx;
        pv1 += W[1536 + d] * fv + W[2048 + d] * avg + W[2560 + d] * mx;
        pv2 += W[3072 + d] * fv + W[3584 + d] * avg + W[4096 + d] * mx;
    }
#pragma unroll
    for (int o = 16; o; o >>= 1) {
        pv0 += __shfl_xor_sync(0xffffffffu, pv0, o);
        pv1 += __shfl_xor_sync(0xffffffffu, pv1, o);
        pv2 += __shfl_xor_sync(0xffffffffu, pv2, o);
    }
    if (lane == 0) { wred[wid] = pv0; wred[8 + wid] = pv1; wred[16 + wid] = pv2; }
    __syncthreads();

    if (tid == 0) {
        float v0 = bvec[0], v1 = bvec[1], v2 = bvec[2];
#pragma unroll
        for (int i = 0; i < 8; i++) { v0 += wred[i]; v1 += wred[8 + i]; v2 += wred[16 + i]; }
        float vin[3] = {v0, v1, v2}, t1[3], t2[3];
        inv3_apply(R1 + (size_t)pt * 9, vin, t1);
        inv3_apply(R2 + (size_t)pt * 9, t1, t2);
        float m = (cen[pt] >= NP) ? 1.0f : 0.0f;
#pragma unroll
        for (int j = 0; j < 3; j++) {
            float qr = q[pt * 3 + j] + t2[j] * m;
            out[49152 + pt * 3 + j] = qr;
            out[98304 + pt * 3 + j] = qr;
        }
    }
}

// ---------------------------------------------------------------------------
// Launch. Inputs: p, q, ffp, ffq, R1, R2, centroids, W, b
// Output: concat(q, q_refine, q_refine, idx) as f32, 409600 elems.
// ---------------------------------------------------------------------------
extern "C" void kernel_launch(void* const* d_in, const int* in_sizes, int n_in,
                              void* d_out, int out_size) {
    const float* q   = (const float*)d_in[1];
    const float* ffp = (const float*)d_in[2];
    const float* ffq = (const float*)d_in[3];
    const float* R1  = (const float*)d_in[4];
    const float* R2  = (const float*)d_in[5];
    const int*   cen = (const int*)d_in[6];
    const float* W   = (const float*)d_in[7];
    const float* bb  = (const float*)d_in[8];
    float* out = (float*)d_out;

    cudaFuncSetAttribute(k_gemm_hmma, cudaFuncAttributeMaxDynamicSharedMemorySize, 65536);

    __half* d_fph; cudaGetSymbolAddress((void**)&d_fph, g_fph);
    __half* d_fqh; cudaGetSymbolAddress((void**)&d_fqh, g_fqh);
    float*  d_gnp; cudaGetSymbolAddress((void**)&d_gnp, g_np);
    float*  d_gnq; cudaGetSymbolAddress((void**)&d_gnq, g_nq);

    dim3 gn(NB * NP / 8, 2);
    k_normalize2<<<gn, 256>>>(ffp, d_fph, d_gnp, ffq, d_fqh, d_gnq);

    dim3 gg(NP / BN, NP / BM, NB);            // (16, 16, 8)
    k_gemm_hmma<<<gg, 256, 65536>>>();

    k_cand<<<NB * NP / 8, 256>>>();

    k_rescore<<<NB * NP / 8, 256>>>(ffp, ffq, out);

    k_pool<<<NB * NP, 256>>>(ffp, ffq, R1, R2, cen, W, bb, q, out);

    cudaMemcpyAsync(out, q, (size_t)NB * NP * 3 * sizeof(float),
                    cudaMemcpyDeviceToDevice);
}

// round 12
// speedup vs baseline: 2.9674x; 1.2027x over previous
#include <cuda_runtime.h>
#include <cuda_fp16.h>
#include <float.h>
#include <math.h>
#include <stdint.h>

#define NB 8
#define NP 2048
#define ND 512
#define NK 16
#define NCAND 32

// ---------------- device scratch (no allocations allowed) -------------------
__device__ __half g_fqh[(size_t)NB * NP * ND];        // normalized ffq, fp16
__device__ __half g_fph[(size_t)NB * NP * ND];        // normalized ffp, fp16
__device__ float  g_nq[NB * NP];                      // 1/(||ffq||+eps)
__device__ float  g_np[NB * NP];                      // 1/(||ffp||+eps)
__device__ __half g_w1h[(size_t)NB * NP * NP];        // similarity, fp16
__device__ int    g_cand[NB * NP * NCAND];            // top-32 candidates per row
__device__ int    g_sel[NB * NP * NK];                // final top-16 (global idx)

// ---------------- helpers ---------------------------------------------------
__device__ __forceinline__ uint32_t smem_u32(const void* p) {
    uint32_t a;
    asm("{ .reg .u64 t; cvta.to.shared.u64 t, %1; cvt.u32.u64 %0, t; }" : "=r"(a) : "l"(p));
    return a;
}
#define SWZ(off) ((off) ^ (((off) >> 3) & 0x70))

__device__ __forceinline__ void cp16(uint32_t dst, const void* src) {
    asm volatile("cp.async.cg.shared.global [%0], [%1], 16;" :: "r"(dst), "l"(src));
}
#define CP_COMMIT() asm volatile("cp.async.commit_group;" ::: "memory")
#define CP_WAIT(n)  asm volatile("cp.async.wait_group %0;" :: "n"(n) : "memory")

#define LDSM4(r, addr)                                                          \
    asm volatile("ldmatrix.sync.aligned.m8n8.x4.shared.b16 {%0,%1,%2,%3}, [%4];" \
        : "=r"((r)[0]), "=r"((r)[1]), "=r"((r)[2]), "=r"((r)[3]) : "r"(addr))

__device__ __forceinline__ void mma16816(float* d, const uint32_t* a,
                                         uint32_t b0, uint32_t b1) {
    asm volatile(
        "mma.sync.aligned.m16n8k16.row.col.f32.f16.f16.f32 "
        "{%0,%1,%2,%3},{%4,%5,%6,%7},{%8,%9},{%0,%1,%2,%3};"
        : "+f"(d[0]), "+f"(d[1]), "+f"(d[2]), "+f"(d[3])
        : "r"(a[0]), "r"(a[1]), "r"(a[2]), "r"(a[3]), "r"(b0), "r"(b1));
}

// ---------------------------------------------------------------------------
// Normalize rows by (L2 + 1e-8) for both tensors in one launch (blockIdx.y
// selects ffp/ffq). Norm reduction = exact validated R1 arithmetic.
// ---------------------------------------------------------------------------
__global__ void k_normalize2(const float* __restrict__ srcp, __half* __restrict__ dstp,
                             float* __restrict__ invnp,
                             const float* __restrict__ srcq, __half* __restrict__ dstq,
                             float* __restrict__ invnq) {
    const float* src = blockIdx.y ? srcq : srcp;
    __half* dst = blockIdx.y ? dstq : dstp;
    float* invn = blockIdx.y ? invnq : invnp;
    int row  = blockIdx.x * 8 + (threadIdx.x >> 5);
    int lane = threadIdx.x & 31;
    const float* s = src + (size_t)row * ND;
    float ss = 0.f;
    for (int d = lane; d < ND; d += 32) { float v = s[d]; ss = fmaf(v, v, ss); }
#pragma unroll
    for (int o = 16; o; o >>= 1) ss += __shfl_xor_sync(0xffffffffu, ss, o);
    float inv = 1.0f / (sqrtf(ss) + 1e-8f);
    if (lane == 0) invn[row] = inv;
    const float2* s2 = (const float2*)s;
    __half2* d2 = (__half2*)(dst + (size_t)row * ND);
#pragma unroll
    for (int i = 0; i < 8; i++) {
        float2 v = s2[lane + 32 * i];
        d2[lane + 32 * i] = __floats2half2_rn(v.x * inv, v.y * inv);
    }
}

// ---------------------------------------------------------------------------
// HMMA fp16 GEMM: w1[b] = fq[b] @ fp[b]^T -> fp16.
// 128x128 tile, BK=64, cp.async double buffer, 8 warps in 4(M) x 2(N),
// warp tile 32x64, mma.m16n8k16, fp32 accumulate.
// ---------------------------------------------------------------------------
#define BM 128
#define BN 128
#define BK 64

__global__ __launch_bounds__(256) void k_gemm_hmma() {
    extern __shared__ char sm[];
    const uint32_t sb = smem_u32(sm);
    const int tid = threadIdx.x, lane = tid & 31, wid = tid >> 5;
    const int wm = wid & 3, wn = wid >> 2;
    const int bz = blockIdx.z;
    const __half* Ag = g_fqh + ((size_t)bz * NP + blockIdx.y * BM) * ND;
    const __half* Bg = g_fph + ((size_t)bz * NP + blockIdx.x * BN) * ND;

    auto load = [&](int kc, int buf) {
        uint32_t abase = sb + buf * 32768;
        const __half* ap = Ag + kc * BK;
#pragma unroll
        for (int i = 0; i < 4; i++) {
            int id = tid + i * 256;
            int r = id >> 3, c = id & 7;
            cp16(abase + SWZ(r * 128 + c * 16), ap + (size_t)r * ND + c * 8);
        }
        uint32_t bbase = abase + 16384;
        const __half* bp = Bg + kc * BK;
#pragma unroll
        for (int i = 0; i < 4; i++) {
            int id = tid + i * 256;
            int r = id >> 3, c = id & 7;
            cp16(bbase + SWZ(r * 128 + c * 16), bp + (size_t)r * ND + c * 8);
        }
    };

    float acc[2][8][4];
#pragma unroll
    for (int t = 0; t < 2; t++)
#pragma unroll
        for (int n = 0; n < 8; n++)
#pragma unroll
            for (int i = 0; i < 4; i++) acc[t][n][i] = 0.f;

    load(0, 0);
    CP_COMMIT();

    const int lrow = lane & 15;
    const int lk16 = (lane >> 4) * 16;

#pragma unroll 1
    for (int c = 0; c < 8; c++) {
        int buf = c & 1;
        if (c < 7) { load(c + 1, buf ^ 1); CP_COMMIT(); CP_WAIT(1); }
        else       { CP_WAIT(0); }
        __syncthreads();
        uint32_t Asb = sb + buf * 32768;
        uint32_t Bsb = Asb + 16384;
#pragma unroll
        for (int ks = 0; ks < 4; ks++) {
            uint32_t a[2][4];
#pragma unroll
            for (int t = 0; t < 2; t++) {
                int row = wm * 32 + t * 16 + lrow;
                uint32_t off = (uint32_t)(row * 128 + ks * 32 + lk16) ^ ((row & 7) << 4);
                LDSM4(a[t], Asb + off);
            }
            uint32_t bfr[4][4];
#pragma unroll
            for (int j = 0; j < 4; j++) {
                int row = wn * 64 + j * 16 + lrow;
                uint32_t off = (uint32_t)(row * 128 + ks * 32 + lk16) ^ ((row & 7) << 4);
                LDSM4(bfr[j], Bsb + off);
            }
#pragma unroll
            for (int t = 0; t < 2; t++)
#pragma unroll
                for (int n8 = 0; n8 < 8; n8++) {
                    int j = n8 >> 1, hi = n8 & 1;
                    mma16816(acc[t][n8], a[t], bfr[j][hi ? 1 : 0], bfr[j][hi ? 3 : 2]);
                }
        }
        __syncthreads();
    }

    const int q0 = blockIdx.y * BM, p0 = blockIdx.x * BN;
#pragma unroll
    for (int t = 0; t < 2; t++)
#pragma unroll
        for (int n8 = 0; n8 < 8; n8++) {
            int m = q0 + wm * 32 + t * 16 + (lane >> 2);
            int n = p0 + wn * 64 + n8 * 8 + (lane & 3) * 2;
            size_t base = ((size_t)bz * NP + m) * NP + n;
            *(__half2*)(g_w1h + base) =
                __floats2half2_rn(acc[t][n8][0], acc[t][n8][1]);
            *(__half2*)(g_w1h + base + (size_t)8 * NP) =
                __floats2half2_rn(acc[t][n8][2], acc[t][n8][3]);
        }
}

// ---------------------------------------------------------------------------
// Per-row top-32 candidates from fp16 w1. One warp per row; row register-
// resident. Per-lane sorted top-4 buffer; butterfly over lane heads; exact
// rescan fallback on buffer exhaustion.
// ---------------------------------------------------------------------------
__global__ __launch_bounds__(256) void k_cand() {
    int row  = blockIdx.x * 8 + (threadIdx.x >> 5);
    int lane = threadIdx.x & 31;
    const unsigned int* rp = ((const unsigned int*)g_w1h) + (size_t)row * (NP / 2);
    unsigned int rv[32];
#pragma unroll
    for (int i = 0; i < 32; i++) rv[i] = rp[i * 32 + lane];

    float bv0 = -FLT_MAX, bv1 = -FLT_MAX, bv2 = -FLT_MAX, bv3 = -FLT_MAX;
    int   bi0 = 1 << 30,  bi1 = 1 << 30,  bi2 = 1 << 30,  bi3 = 1 << 30;

    auto ins = [&](float v, int id) {
        if (v > bv3) {
            if (v > bv1) {
                if (v > bv0) {
                    bv3 = bv2; bi3 = bi2; bv2 = bv1; bi2 = bi1;
                    bv1 = bv0; bi1 = bi0; bv0 = v;  bi0 = id;
                } else {
                    bv3 = bv2; bi3 = bi2; bv2 = bv1; bi2 = bi1;
                    bv1 = v;  bi1 = id;
                }
            } else {
                if (v > bv2) { bv3 = bv2; bi3 = bi2; bv2 = v; bi2 = id; }
                else         { bv3 = v;  bi3 = id; }
            }
        }
    };
    auto build = [&]() {
        bv0 = bv1 = bv2 = bv3 = -FLT_MAX;
        bi0 = bi1 = bi2 = bi3 = 1 << 30;
#pragma unroll
        for (int i = 0; i < 32; i++) {
            float2 f = __half22float2(*(__half2*)&rv[i]);
            int base = (i * 32 + lane) << 1;
            ins(f.x, base);
            ins(f.y, base + 1);
        }
    };
    build();

    int* outc = g_cand + (size_t)row * NCAND;
#pragma unroll 1
    for (int it = 0; it < NCAND; it++) {
        float wv = bv0; int wi = bi0;
#pragma unroll
        for (int o = 16; o; o >>= 1) {
            float ov = __shfl_xor_sync(0xffffffffu, wv, o);
            int   oi = __shfl_xor_sync(0xffffffffu, wi, o);
            if (ov > wv || (ov == wv && oi < wi)) { wv = ov; wi = oi; }
        }
        if (lane == 0) outc[it] = wi;
        if (bi0 == wi) {
            int slot = wi >> 6;
            __half2 h = *(__half2*)&rv[slot];
            if (wi & 1) h.y = __ushort_as_half((unsigned short)0xFC00);
            else        h.x = __ushort_as_half((unsigned short)0xFC00);
            rv[slot] = *(unsigned int*)&h;
            bv0 = bv1; bi0 = bi1; bv1 = bv2; bi1 = bi2;
            bv2 = bv3; bi2 = bi3; bv3 = -FLT_MAX; bi3 = 1 << 30;
            if (bv0 == -FLT_MAX) build();
        }
    }
}

// ---------------------------------------------------------------------------
// Exact rescore + sort. One WARP per point (8 points/block). d processed in
// 16 chunks of 32: the warp cooperatively stages a 32x32 (candidate x d) tile
// with fully-coalesced loads (one 128B line per row), then each lane runs its
// bit-identical sequential mul->fmaf chain for its own candidate out of smem
// (stride-33, conflict-free). Bitonic sort (desc value, asc index); writes
// winner indices to g_sel and the float idx output.
// ---------------------------------------------------------------------------
__global__ __launch_bounds__(256) void k_rescore(
    const float* __restrict__ ffp, const float* __restrict__ ffq,
    float* __restrict__ out)
{
    __shared__ float sfq[8][ND];              // 16 KB
    __shared__ float stile[8][32][33];        // 33.8 KB
    const int wid = threadIdx.x >> 5, lane = threadIdx.x & 31;
    const int pt = blockIdx.x * 8 + wid;
    const int b = pt >> 11;

    // stage normalized fq row (once-rounded fp32, same arithmetic as before)
    const float4* fq4 = (const float4*)(ffq + (size_t)pt * ND);
    float invq = g_nq[pt];
    float4* sq4 = (float4*)sfq[wid];
#pragma unroll
    for (int i = 0; i < 4; i++) {
        float4 v = fq4[lane + 32 * i];
        v.x *= invq; v.y *= invq; v.z *= invq; v.w *= invq;
        sq4[lane + 32 * i] = v;
    }
    __syncwarp();

    const int ci = g_cand[(size_t)pt * NCAND + lane];
    const float invp = g_np[b * NP + ci];
    const float* fpb = ffp + (size_t)b * NP * ND;
    float (*tile)[33] = stile[wid];
    const float* sq = sfq[wid];

    float acc = 0.f;
#pragma unroll 1
    for (int ch = 0; ch < 16; ch++) {
        // coalesced stage: row r of the tile = candidate r's d-chunk
#pragma unroll
        for (int r = 0; r < 32; r++) {
            int cir = __shfl_sync(0xffffffffu, ci, r);
            tile[r][lane] = __ldg(fpb + (size_t)cir * ND + ch * 32 + lane);
        }
        __syncwarp();
        // sequential chain for this lane's candidate
#pragma unroll
        for (int dd = 0; dd < 32; dd++) {
            float t = tile[lane][dd] * invp;       // once-rounded normalized elem
            acc = fmaf(t, sq[ch * 32 + dd], acc);  // strictly sequential, fused
        }
        __syncwarp();
    }

    unsigned int u = __float_as_uint(acc);
    unsigned int ou = (u & 0x80000000u) ? ~u : (u | 0x80000000u);
    unsigned long long key =
        ((unsigned long long)(~ou) << 32) | (unsigned)((ci << 5) | lane);
#pragma unroll
    for (int k = 2; k <= 32; k <<= 1) {
#pragma unroll
        for (int j = k >> 1; j > 0; j >>= 1) {
            unsigned long long o = __shfl_xor_sync(0xffffffffu, key, j);
            bool dirUp = ((lane & k) == 0);
            bool lower = ((lane & j) == 0);
            unsigned long long mn = (key < o) ? key : o;
            unsigned long long mx = (key < o) ? o : key;
            key = (lower == dirUp) ? mn : mx;
        }
    }
    if (lane < NK) {
        int idx = (int)((key >> 5) & 2047u);
        g_sel[pt * NK + lane] = idx;
        out[3 * NB * NP * 3 + pt * NK + lane] = (float)idx;
    }
}

// ---------------------------------------------------------------------------
// 3x3 inverse (adjugate) applied to a vector.
// ---------------------------------------------------------------------------
__device__ __forceinline__ void inv3_apply(const float* __restrict__ M,
                                           const float* __restrict__ v,
                                           float* __restrict__ o) {
    float a = M[0], b = M[1], c = M[2];
    float d = M[3], e = M[4], f = M[5];
    float g = M[6], h = M[7], i = M[8];
    float A  = e * i - f * h;
    float Bc = -(d * i - f * g);
    float Cc = d * h - e * g;
    float det = a * A + b * Bc + c * Cc;
    float id = 1.0f / det;
    float i00 = A * id,  i01 = -(b * i - c * h) * id, i02 = (b * f - c * e) * id;
    float i10 = Bc * id, i11 = (a * i - c * g) * id,  i12 = -(a * f - c * d) * id;
    float i20 = Cc * id, i21 = -(a * h - b * g) * id, i22 = (a * e - b * d) * id;
    o[0] = i00 * v[0] + i01 * v[1] + i02 * v[2];
    o[1] = i10 * v[0] + i11 * v[1] + i12 * v[2];
    o[2] = i20 * v[0] + i21 * v[1] + i22 * v[2];
}

// ---------------------------------------------------------------------------
// Pool (avg/max over the 16 winners, read straight from L2, coalesced) +
// refine linear + inv(R1),inv(R2) rotate-back + mask + add q.
// One block per point, no candidate staging -> high occupancy.
// ---------------------------------------------------------------------------
__global__ __launch_bounds__(256) void k_pool(
    const float* __restrict__ ffp, const float* __restrict__ ffq,
    const float* __restrict__ R1,  const float* __restrict__ R2,
    const int*   __restrict__ cen, const float* __restrict__ W,
    const float* __restrict__ bvec, const float* __restrict__ q,
    float* __restrict__ out)
{
    __shared__ int   ssel[NK];
    __shared__ float wred[24];
    const int pt = blockIdx.x, b = pt >> 11;
    const int tid = threadIdx.x, lane = tid & 31, wid = tid >> 5;

    if (tid < NK) ssel[tid] = g_sel[pt * NK + tid];
    __syncthreads();

    const float* fpb = ffp + (size_t)b * NP * ND;
    const float* fqr = ffq + (size_t)pt * ND;

    float pv0 = 0.f, pv1 = 0.f, pv2 = 0.f;
#pragma unroll
    for (int rr = 0; rr < 2; rr++) {
        int d = tid + rr * 256;
        float s = 0.f, mx = -FLT_MAX;
#pragma unroll
        for (int k = 0; k < NK; k++) {
            float v = __ldg(fpb + (size_t)ssel[k] * ND + d);
            s += v;
            mx = fmaxf(mx, v);
        }
        float avg = s * (1.0f / 16.0f);
        float fv  = fqr[d];
        pv0 += W[d] * fv        + W[512 + d] * avg  + W[1024 + d] * mx;
        pv1 += W[1536 + d] * fv + W[2048 + d] * avg + W[2560 + d] * mx;
        pv2 += W[3072 + d] * fv + W[3584 + d] * avg + W[4096 + d] * mx;
    }
#pragma unroll
    for (int o = 16; o; o >>= 1) {
        pv0 += __shfl_xor_sync(0xffffffffu, pv0, o);
        pv1 += __shfl_xor_sync(0xffffffffu, pv1, o);
        pv2 += __shfl_xor_sync(0xffffffffu, pv2, o);
    }
    if (lane == 0) { wred[wid] = pv0; wred[8 + wid] = pv1; wred[16 + wid] = pv2; }
    __syncthreads();

    if (tid == 0) {
        float v0 = bvec[0], v1 = bvec[1], v2 = bvec[2];
#pragma unroll
        for (int i = 0; i < 8; i++) { v0 += wred[i]; v1 += wred[8 + i]; v2 += wred[16 + i]; }
        float vin[3] = {v0, v1, v2}, t1[3], t2[3];
        inv3_apply(R1 + (size_t)pt * 9, vin, t1);
        inv3_apply(R2 + (size_t)pt * 9, t1, t2);
        float m = (cen[pt] >= NP) ? 1.0f : 0.0f;
#pragma unroll
        for (int j = 0; j < 3; j++) {
            float qr = q[pt * 3 + j] + t2[j] * m;
            out[49152 + pt * 3 + j] = qr;
            out[98304 + pt * 3 + j] = qr;
        }
    }
}

// ---------------------------------------------------------------------------
// Launch. Inputs: p, q, ffp, ffq, R1, R2, centroids, W, b
// Output: concat(q, q_refine, q_refine, idx) as f32, 409600 elems.
// ---------------------------------------------------------------------------
extern "C" void kernel_launch(void* const* d_in, const int* in_sizes, int n_in,
                              void* d_out, int out_size) {
    const float* q   = (const float*)d_in[1];
    const float* ffp = (const float*)d_in[2];
    const float* ffq = (const float*)d_in[3];
    const float* R1  = (const float*)d_in[4];
    const float* R2  = (const float*)d_in[5];
    const int*   cen = (const int*)d_in[6];
    const float* W   = (const float*)d_in[7];
    const float* bb  = (const float*)d_in[8];
    float* out = (float*)d_out;

    cudaFuncSetAttribute(k_gemm_hmma, cudaFuncAttributeMaxDynamicSharedMemorySize, 65536);

    __half* d_fph; cudaGetSymbolAddress((void**)&d_fph, g_fph);
    __half* d_fqh; cudaGetSymbolAddress((void**)&d_fqh, g_fqh);
    float*  d_gnp; cudaGetSymbolAddress((void**)&d_gnp, g_np);
    float*  d_gnq; cudaGetSymbolAddress((void**)&d_gnq, g_nq);

    dim3 gn(NB * NP / 8, 2);
    k_normalize2<<<gn, 256>>>(ffp, d_fph, d_gnp, ffq, d_fqh, d_gnq);

    dim3 gg(NP / BN, NP / BM, NB);            // (16, 16, 8)
    k_gemm_hmma<<<gg, 256, 65536>>>();

    k_cand<<<NB * NP / 8, 256>>>();

    k_rescore<<<NB * NP / 8, 256>>>(ffp, ffq, out);

    k_pool<<<NB * NP, 256>>>(ffp, ffq, R1, R2, cen, W, bb, q, out);

    cudaMemcpyAsync(out, q, (size_t)NB * NP * 3 * sizeof(float),
                    cudaMemcpyDeviceToDevice);
}

// round 13
// speedup vs baseline: 3.6242x; 1.2213x over previous
#include <cuda_runtime.h>
#include <cuda_fp16.h>
#include <float.h>
#include <math.h>
#include <stdint.h>

#define NB 8
#define NP 2048
#define ND 512
#define NK 16
#define NCAND 32

// ---------------- device scratch (no allocations allowed) -------------------
__device__ __half g_fqh[(size_t)NB * NP * ND];        // normalized ffq, fp16
__device__ __half g_fph[(size_t)NB * NP * ND];        // normalized ffp, fp16
__device__ float  g_nq[NB * NP];                      // 1/(||ffq||+eps)
__device__ float  g_np[NB * NP];                      // 1/(||ffp||+eps)
__device__ __half g_w1h[(size_t)NB * NP * NP];        // similarity, fp16
__device__ int    g_cand[NB * NP * NCAND];            // top-32 candidates per row
__device__ int    g_sel[NB * NP * NK];                // final top-16 (global idx)

// ---------------- helpers ---------------------------------------------------
__device__ __forceinline__ uint32_t smem_u32(const void* p) {
    uint32_t a;
    asm("{ .reg .u64 t; cvta.to.shared.u64 t, %1; cvt.u32.u64 %0, t; }" : "=r"(a) : "l"(p));
    return a;
}
#define SWZ(off) ((off) ^ (((off) >> 3) & 0x70))

__device__ __forceinline__ void cp16(uint32_t dst, const void* src) {
    asm volatile("cp.async.cg.shared.global [%0], [%1], 16;" :: "r"(dst), "l"(src));
}
#define CP_COMMIT() asm volatile("cp.async.commit_group;" ::: "memory")
#define CP_WAIT(n)  asm volatile("cp.async.wait_group %0;" :: "n"(n) : "memory")

#define LDSM4(r, addr)                                                          \
    asm volatile("ldmatrix.sync.aligned.m8n8.x4.shared.b16 {%0,%1,%2,%3}, [%4];" \
        : "=r"((r)[0]), "=r"((r)[1]), "=r"((r)[2]), "=r"((r)[3]) : "r"(addr))

__device__ __forceinline__ void mma16816(float* d, const uint32_t* a,
                                         uint32_t b0, uint32_t b1) {
    asm volatile(
        "mma.sync.aligned.m16n8k16.row.col.f32.f16.f16.f32 "
        "{%0,%1,%2,%3},{%4,%5,%6,%7},{%8,%9},{%0,%1,%2,%3};"
        : "+f"(d[0]), "+f"(d[1]), "+f"(d[2]), "+f"(d[3])
        : "r"(a[0]), "r"(a[1]), "r"(a[2]), "r"(a[3]), "r"(b0), "r"(b1));
}

// ---------------------------------------------------------------------------
// Normalize rows by (L2 + 1e-8) for both tensors in one launch (blockIdx.y
// selects ffp/ffq). Norm reduction = exact validated R1 arithmetic.
// ---------------------------------------------------------------------------
__global__ void k_normalize2(const float* __restrict__ srcp, __half* __restrict__ dstp,
                             float* __restrict__ invnp,
                             const float* __restrict__ srcq, __half* __restrict__ dstq,
                             float* __restrict__ invnq) {
    const float* src = blockIdx.y ? srcq : srcp;
    __half* dst = blockIdx.y ? dstq : dstp;
    float* invn = blockIdx.y ? invnq : invnp;
    int row  = blockIdx.x * 8 + (threadIdx.x >> 5);
    int lane = threadIdx.x & 31;
    const float* s = src + (size_t)row * ND;
    float ss = 0.f;
    for (int d = lane; d < ND; d += 32) { float v = s[d]; ss = fmaf(v, v, ss); }
#pragma unroll
    for (int o = 16; o; o >>= 1) ss += __shfl_xor_sync(0xffffffffu, ss, o);
    float inv = 1.0f / (sqrtf(ss) + 1e-8f);
    if (lane == 0) invn[row] = inv;
    const float2* s2 = (const float2*)s;
    __half2* d2 = (__half2*)(dst + (size_t)row * ND);
#pragma unroll
    for (int i = 0; i < 8; i++) {
        float2 v = s2[lane + 32 * i];
        d2[lane + 32 * i] = __floats2half2_rn(v.x * inv, v.y * inv);
    }
}

// ---------------------------------------------------------------------------
// HMMA fp16 GEMM: w1[b] = fq[b] @ fp[b]^T -> fp16.
// 128x128 tile, BK=64, cp.async double buffer, 8 warps in 4(M) x 2(N),
// warp tile 32x64, mma.m16n8k16, fp32 accumulate.
// ---------------------------------------------------------------------------
#define BM 128
#define BN 128
#define BK 64

__global__ __launch_bounds__(256) void k_gemm_hmma() {
    extern __shared__ char sm[];
    const uint32_t sb = smem_u32(sm);
    const int tid = threadIdx.x, lane = tid & 31, wid = tid >> 5;
    const int wm = wid & 3, wn = wid >> 2;
    const int bz = blockIdx.z;
    const __half* Ag = g_fqh + ((size_t)bz * NP + blockIdx.y * BM) * ND;
    const __half* Bg = g_fph + ((size_t)bz * NP + blockIdx.x * BN) * ND;

    auto load = [&](int kc, int buf) {
        uint32_t abase = sb + buf * 32768;
        const __half* ap = Ag + kc * BK;
#pragma unroll
        for (int i = 0; i < 4; i++) {
            int id = tid + i * 256;
            int r = id >> 3, c = id & 7;
            cp16(abase + SWZ(r * 128 + c * 16), ap + (size_t)r * ND + c * 8);
        }
        uint32_t bbase = abase + 16384;
        const __half* bp = Bg + kc * BK;
#pragma unroll
        for (int i = 0; i < 4; i++) {
            int id = tid + i * 256;
            int r = id >> 3, c = id & 7;
            cp16(bbase + SWZ(r * 128 + c * 16), bp + (size_t)r * ND + c * 8);
        }
    };

    float acc[2][8][4];
#pragma unroll
    for (int t = 0; t < 2; t++)
#pragma unroll
        for (int n = 0; n < 8; n++)
#pragma unroll
            for (int i = 0; i < 4; i++) acc[t][n][i] = 0.f;

    load(0, 0);
    CP_COMMIT();

    const int lrow = lane & 15;
    const int lk16 = (lane >> 4) * 16;

#pragma unroll 1
    for (int c = 0; c < 8; c++) {
        int buf = c & 1;
        if (c < 7) { load(c + 1, buf ^ 1); CP_COMMIT(); CP_WAIT(1); }
        else       { CP_WAIT(0); }
        __syncthreads();
        uint32_t Asb = sb + buf * 32768;
        uint32_t Bsb = Asb + 16384;
#pragma unroll
        for (int ks = 0; ks < 4; ks++) {
            uint32_t a[2][4];
#pragma unroll
            for (int t = 0; t < 2; t++) {
                int row = wm * 32 + t * 16 + lrow;
                uint32_t off = (uint32_t)(row * 128 + ks * 32 + lk16) ^ ((row & 7) << 4);
                LDSM4(a[t], Asb + off);
            }
            uint32_t bfr[4][4];
#pragma unroll
            for (int j = 0; j < 4; j++) {
                int row = wn * 64 + j * 16 + lrow;
                uint32_t off = (uint32_t)(row * 128 + ks * 32 + lk16) ^ ((row & 7) << 4);
                LDSM4(bfr[j], Bsb + off);
            }
#pragma unroll
            for (int t = 0; t < 2; t++)
#pragma unroll
                for (int n8 = 0; n8 < 8; n8++) {
                    int j = n8 >> 1, hi = n8 & 1;
                    mma16816(acc[t][n8], a[t], bfr[j][hi ? 1 : 0], bfr[j][hi ? 3 : 2]);
                }
        }
        __syncthreads();
    }

    const int q0 = blockIdx.y * BM, p0 = blockIdx.x * BN;
#pragma unroll
    for (int t = 0; t < 2; t++)
#pragma unroll
        for (int n8 = 0; n8 < 8; n8++) {
            int m = q0 + wm * 32 + t * 16 + (lane >> 2);
            int n = p0 + wn * 64 + n8 * 8 + (lane & 3) * 2;
            size_t base = ((size_t)bz * NP + m) * NP + n;
            *(__half2*)(g_w1h + base) =
                __floats2half2_rn(acc[t][n8][0], acc[t][n8][1]);
            *(__half2*)(g_w1h + base + (size_t)8 * NP) =
                __floats2half2_rn(acc[t][n8][2], acc[t][n8][3]);
        }
}

// ---------------------------------------------------------------------------
// Per-row top-32 candidates from fp16 w1. One warp per row; row register-
// resident. Per-lane sorted top-4 buffer; butterfly over lane heads; exact
// rescan fallback on buffer exhaustion.
// ---------------------------------------------------------------------------
__global__ __launch_bounds__(256) void k_cand() {
    int row  = blockIdx.x * 8 + (threadIdx.x >> 5);
    int lane = threadIdx.x & 31;
    const unsigned int* rp = ((const unsigned int*)g_w1h) + (size_t)row * (NP / 2);
    unsigned int rv[32];
#pragma unroll
    for (int i = 0; i < 32; i++) rv[i] = rp[i * 32 + lane];

    float bv0 = -FLT_MAX, bv1 = -FLT_MAX, bv2 = -FLT_MAX, bv3 = -FLT_MAX;
    int   bi0 = 1 << 30,  bi1 = 1 << 30,  bi2 = 1 << 30,  bi3 = 1 << 30;

    auto ins = [&](float v, int id) {
        if (v > bv3) {
            if (v > bv1) {
                if (v > bv0) {
                    bv3 = bv2; bi3 = bi2; bv2 = bv1; bi2 = bi1;
                    bv1 = bv0; bi1 = bi0; bv0 = v;  bi0 = id;
                } else {
                    bv3 = bv2; bi3 = bi2; bv2 = bv1; bi2 = bi1;
                    bv1 = v;  bi1 = id;
                }
            } else {
                if (v > bv2) { bv3 = bv2; bi3 = bi2; bv2 = v; bi2 = id; }
                else         { bv3 = v;  bi3 = id; }
            }
        }
    };
    auto build = [&]() {
        bv0 = bv1 = bv2 = bv3 = -FLT_MAX;
        bi0 = bi1 = bi2 = bi3 = 1 << 30;
#pragma unroll
        for (int i = 0; i < 32; i++) {
            float2 f = __half22float2(*(__half2*)&rv[i]);
            int base = (i * 32 + lane) << 1;
            ins(f.x, base);
            ins(f.y, base + 1);
        }
    };
    build();

    int* outc = g_cand + (size_t)row * NCAND;
#pragma unroll 1
    for (int it = 0; it < NCAND; it++) {
        float wv = bv0; int wi = bi0;
#pragma unroll
        for (int o = 16; o; o >>= 1) {
            float ov = __shfl_xor_sync(0xffffffffu, wv, o);
            int   oi = __shfl_xor_sync(0xffffffffu, wi, o);
            if (ov > wv || (ov == wv && oi < wi)) { wv = ov; wi = oi; }
        }
        if (lane == 0) outc[it] = wi;
        if (bi0 == wi) {
            int slot = wi >> 6;
            __half2 h = *(__half2*)&rv[slot];
            if (wi & 1) h.y = __ushort_as_half((unsigned short)0xFC00);
            else        h.x = __ushort_as_half((unsigned short)0xFC00);
            rv[slot] = *(unsigned int*)&h;
            bv0 = bv1; bi0 = bi1; bv1 = bv2; bi1 = bi2;
            bv2 = bv3; bi2 = bi3; bv3 = -FLT_MAX; bi3 = 1 << 30;
            if (bv0 == -FLT_MAX) build();
        }
    }
}

// ---------------------------------------------------------------------------
// Exact rescore + sort. One WARP per point (8 points/block). d processed in
// 16 chunks of 32. Staging via cp.async into per-warp double-buffered tiles
// with 16B XOR swizzle (part ^ (r&7)); consumption via conflict-free LDS.128.
// fq broadcast via registers + shfl (same once-rounded fq[d]*invq values).
// The per-candidate mul->fmaf chain over d=0..511 is bit-identical to the
// validated kernel. Bitonic sort (desc value, asc index).
// ---------------------------------------------------------------------------
__global__ __launch_bounds__(256) void k_rescore(
    const float* __restrict__ ffp, const float* __restrict__ ffq,
    float* __restrict__ out)
{
    __shared__ __align__(16) float stile[8][2][32 * 32];   // 8 warps x 2 bufs x 4KB
    const int wid = threadIdx.x >> 5, lane = threadIdx.x & 31;
    const int pt = blockIdx.x * 8 + wid;
    const int b = pt >> 11;

    // fq chunk values in registers: rqv[ch] = fq[ch*32 + lane] * invq
    const float* fqr = ffq + (size_t)pt * ND;
    const float invq = g_nq[pt];
    float rqv[16];
#pragma unroll
    for (int i = 0; i < 16; i++) rqv[i] = fqr[i * 32 + lane] * invq;

    const int ci = g_cand[(size_t)pt * NCAND + lane];
    const float invp = g_np[b * NP + ci];
    const float* fpb = ffp + (size_t)b * NP * ND;

    const int part = lane & 7;
    const int rbase = lane >> 3;                 // r = i*4 + rbase
    const uint32_t tb0 = smem_u32(stile[wid][0]);
    const uint32_t tb1 = smem_u32(stile[wid][1]);
    const int lsw = lane & 7;                    // read-side swizzle key

    auto stage = [&](int ch, int buf) {
        uint32_t tb = buf ? tb1 : tb0;
#pragma unroll
        for (int i = 0; i < 8; i++) {
            int r = i * 4 + rbase;
            int cir = __shfl_sync(0xffffffffu, ci, r);
            const float* src = fpb + (size_t)cir * ND + ch * 32 + part * 4;
            uint32_t dst = tb + (uint32_t)(r * 128 + ((part ^ (r & 7)) << 4));
            cp16(dst, src);
        }
    };

    stage(0, 0);
    CP_COMMIT();

    float acc = 0.f;
#pragma unroll
    for (int ch = 0; ch < 16; ch++) {
        const int buf = ch & 1;
        if (ch < 15) { stage(ch + 1, buf ^ 1); CP_COMMIT(); CP_WAIT(1); }
        else         { CP_WAIT(0); }
        __syncwarp();
        const float* tb = (const float*)(buf ? stile[wid][1] : stile[wid][0]) + lane * 32;
#pragma unroll
        for (int j = 0; j < 8; j++) {
            float4 v = *(const float4*)(tb + ((j ^ lsw) << 2));
            float s0 = __shfl_sync(0xffffffffu, rqv[ch], j * 4 + 0);
            float s1 = __shfl_sync(0xffffffffu, rqv[ch], j * 4 + 1);
            float s2 = __shfl_sync(0xffffffffu, rqv[ch], j * 4 + 2);
            float s3 = __shfl_sync(0xffffffffu, rqv[ch], j * 4 + 3);
            acc = fmaf(v.x * invp, s0, acc);     // strictly sequential, fused
            acc = fmaf(v.y * invp, s1, acc);
            acc = fmaf(v.z * invp, s2, acc);
            acc = fmaf(v.w * invp, s3, acc);
        }
        __syncwarp();
    }

    unsigned int u = __float_as_uint(acc);
    unsigned int ou = (u & 0x80000000u) ? ~u : (u | 0x80000000u);
    unsigned long long key =
        ((unsigned long long)(~ou) << 32) | (unsigned)((ci << 5) | lane);
#pragma unroll
    for (int k = 2; k <= 32; k <<= 1) {
#pragma unroll
        for (int j = k >> 1; j > 0; j >>= 1) {
            unsigned long long o = __shfl_xor_sync(0xffffffffu, key, j);
            bool dirUp = ((lane & k) == 0);
            bool lower = ((lane & j) == 0);
            unsigned long long mn = (key < o) ? key : o;
            unsigned long long mx = (key < o) ? o : key;
            key = (lower == dirUp) ? mn : mx;
        }
    }
    if (lane < NK) {
        int idx = (int)((key >> 5) & 2047u);
        g_sel[pt * NK + lane] = idx;
        out[3 * NB * NP * 3 + pt * NK + lane] = (float)idx;
    }
}

// ---------------------------------------------------------------------------
// 3x3 inverse (adjugate) applied to a vector.
// ---------------------------------------------------------------------------
__device__ __forceinline__ void inv3_apply(const float* __restrict__ M,
                                           const float* __restrict__ v,
                                           float* __restrict__ o) {
    float a = M[0], b = M[1], c = M[2];
    float d = M[3], e = M[4], f = M[5];
    float g = M[6], h = M[7], i = M[8];
    float A  = e * i - f * h;
    float Bc = -(d * i - f * g);
    float Cc = d * h - e * g;
    float det = a * A + b * Bc + c * Cc;
    float id = 1.0f / det;
    float i00 = A * id,  i01 = -(b * i - c * h) * id, i02 = (b * f - c * e) * id;
    float i10 = Bc * id, i11 = (a * i - c * g) * id,  i12 = -(a * f - c * d) * id;
    float i20 = Cc * id, i21 = -(a * h - b * g) * id, i22 = (a * e - b * d) * id;
    o[0] = i00 * v[0] + i01 * v[1] + i02 * v[2];
    o[1] = i10 * v[0] + i11 * v[1] + i12 * v[2];
    o[2] = i20 * v[0] + i21 * v[1] + i22 * v[2];
}

// ---------------------------------------------------------------------------
// Pool (avg/max over the 16 winners, read straight from L2, coalesced) +
// refine linear + inv(R1),inv(R2) rotate-back + mask + add q.
// One block per point, no candidate staging -> high occupancy.
// ---------------------------------------------------------------------------
__global__ __launch_bounds__(256) void k_pool(
    const float* __restrict__ ffp, const float* __restrict__ ffq,
    const float* __restrict__ R1,  const float* __restrict__ R2,
    const int*   __restrict__ cen, const float* __restrict__ W,
    const float* __restrict__ bvec, const float* __restrict__ q,
    float* __restrict__ out)
{
    __shared__ int   ssel[NK];
    __shared__ float wred[24];
    const int pt = blockIdx.x, b = pt >> 11;
    const int tid = threadIdx.x, lane = tid & 31, wid = tid >> 5;

    if (tid < NK) ssel[tid] = g_sel[pt * NK + tid];
    __syncthreads();

    const float* fpb = ffp + (size_t)b * NP * ND;
    const float* fqr = ffq + (size_t)pt * ND;

    float pv0 = 0.f, pv1 = 0.f, pv2 = 0.f;
#pragma unroll
    for (int rr = 0; rr < 2; rr++) {
        int d = tid + rr * 256;
        float s = 0.f, mx = -FLT_MAX;
#pragma unroll
        for (int k = 0; k < NK; k++) {
            float v = __ldg(fpb + (size_t)ssel[k] * ND + d);
            s += v;
            mx = fmaxf(mx, v);
        }
        float avg = s * (1.0f / 16.0f);
        float fv  = fqr[d];
        pv0 += W[d] * fv        + W[512 + d] * avg  + W[1024 + d] * mx;
        pv1 += W[1536 + d] * fv + W[2048 + d] * avg + W[2560 + d] * mx;
        pv2 += W[3072 + d] * fv + W[3584 + d] * avg + W[4096 + d] * mx;
    }
#pragma unroll
    for (int o = 16; o; o >>= 1) {
        pv0 += __shfl_xor_sync(0xffffffffu, pv0, o);
        pv1 += __shfl_xor_sync(0xffffffffu, pv1, o);
        pv2 += __shfl_xor_sync(0xffffffffu, pv2, o);
    }
    if (lane == 0) { wred[wid] = pv0; wred[8 + wid] = pv1; wred[16 + wid] = pv2; }
    __syncthreads();

    if (tid == 0) {
        float v0 = bvec[0], v1 = bvec[1], v2 = bvec[2];
#pragma unroll
        for (int i = 0; i < 8; i++) { v0 += wred[i]; v1 += wred[8 + i]; v2 += wred[16 + i]; }
        float vin[3] = {v0, v1, v2}, t1[3], t2[3];
        inv3_apply(R1 + (size_t)pt * 9, vin, t1);
        inv3_apply(R2 + (size_t)pt * 9, t1, t2);
        float m = (cen[pt] >= NP) ? 1.0f : 0.0f;
#pragma unroll
        for (int j = 0; j < 3; j++) {
            float qr = q[pt * 3 + j] + t2[j] * m;
            out[49152 + pt * 3 + j] = qr;
            out[98304 + pt * 3 + j] = qr;
        }
    }
}

// ---------------------------------------------------------------------------
// Launch. Inputs: p, q, ffp, ffq, R1, R2, centroids, W, b
// Output: concat(q, q_refine, q_refine, idx) as f32, 409600 elems.
// ---------------------------------------------------------------------------
extern "C" void kernel_launch(void* const* d_in, const int* in_sizes, int n_in,
                              void* d_out, int out_size) {
    const float* q   = (const float*)d_in[1];
    const float* ffp = (const float*)d_in[2];
    const float* ffq = (const float*)d_in[3];
    const float* R1  = (const float*)d_in[4];
    const float* R2  = (const float*)d_in[5];
    const int*   cen = (const int*)d_in[6];
    const float* W   = (const float*)d_in[7];
    const float* bb  = (const float*)d_in[8];
    float* out = (float*)d_out;

    cudaFuncSetAttribute(k_gemm_hmma, cudaFuncAttributeMaxDynamicSharedMemorySize, 65536);

    __half* d_fph; cudaGetSymbolAddress((void**)&d_fph, g_fph);
    __half* d_fqh; cudaGetSymbolAddress((void**)&d_fqh, g_fqh);
    float*  d_gnp; cudaGetSymbolAddress((void**)&d_gnp, g_np);
    float*  d_gnq; cudaGetSymbolAddress((void**)&d_gnq, g_nq);

    dim3 gn(NB * NP / 8, 2);
    k_normalize2<<<gn, 256>>>(ffp, d_fph, d_gnp, ffq, d_fqh, d_gnq);

    dim3 gg(NP / BN, NP / BM, NB);            // (16, 16, 8)
    k_gemm_hmma<<<gg, 256, 65536>>>();

    k_cand<<<NB * NP / 8, 256>>>();

    k_rescore<<<NB * NP / 8, 256>>>(ffp, ffq, out);

    k_pool<<<NB * NP, 256>>>(ffp, ffq, R1, R2, cen, W, bb, q, out);

    cudaMemcpyAsync(out, q, (size_t)NB * NP * 3 * sizeof(float),
                    cudaMemcpyDeviceToDevice);
}